// round 1
// baseline (speedup 1.0000x reference)
#include <cuda_runtime.h>
#include <cuda_bf16.h>

// Problem constants
constexpr int B_  = 2;
constexpr int T_  = 2048;
constexpr int S_  = 2048;
constexpr int D_  = 512;
constexpr int H_  = 8;
constexpr int HS_ = 64;

// Scratch (device globals; no dynamic allocation allowed)
__device__ float g_Q [B_*H_*T_*HS_];   // [B,H,T,HS]
__device__ float g_K [B_*H_*S_*HS_];   // [B,H,S,HS]
__device__ float g_V [B_*H_*S_*HS_];   // [B,H,S,HS]
__device__ float g_MH[B_*T_*H_*HS_];   // [B,T,H,HS]

// ---------------------------------------------------------------------------
// Kernel 1: QKV projection.  For each (b,h,which): O[T,64] = X[b][T,512] @ W[h][512,64]
// grid = (T/64, H, B*3), block = 256.  64x64 tile, k-chunk 32, 4x4 microtile.
// ---------------------------------------------------------------------------
__global__ __launch_bounds__(256) void qkv_proj_kernel(
    const float* __restrict__ xq, const float* __restrict__ xk, const float* __restrict__ xv,
    const float* __restrict__ wq, const float* __restrict__ wk, const float* __restrict__ wv)
{
    __shared__ float As[64][33];
    __shared__ float Ws[32][68];

    const int which = blockIdx.z % 3;
    const int b     = blockIdx.z / 3;
    const int h     = blockIdx.y;
    const int row0  = blockIdx.x * 64;

    const float* X; const float* W; float* O; float scale;
    if (which == 0)      { X = xq; W = wq; O = g_Q; scale = 0.125f; } // 1/sqrt(HS)
    else if (which == 1) { X = xk; W = wk; O = g_K; scale = 1.0f; }
    else                 { X = xv; W = wv; O = g_V; scale = 1.0f; }

    X += (size_t)b * T_ * D_;
    W += (size_t)h * D_ * HS_;
    O += (size_t)(b * H_ + h) * T_ * HS_;

    const int tid = threadIdx.x;
    const int tx  = tid & 15;
    const int ty  = tid >> 4;

    float acc[4][4] = {};

    for (int k0 = 0; k0 < D_; k0 += 32) {
        #pragma unroll
        for (int i = 0; i < 8; i++) {
            int idx = tid + i * 256;
            int r = idx >> 5, c = idx & 31;
            As[r][c] = X[(size_t)(row0 + r) * D_ + k0 + c];
        }
        #pragma unroll
        for (int i = 0; i < 8; i++) {
            int idx = tid + i * 256;
            int r = idx >> 6, c = idx & 63;
            Ws[r][c] = W[(size_t)(k0 + r) * HS_ + c];
        }
        __syncthreads();

        #pragma unroll
        for (int kk = 0; kk < 32; kk++) {
            float a0 = As[ty*4+0][kk];
            float a1 = As[ty*4+1][kk];
            float a2 = As[ty*4+2][kk];
            float a3 = As[ty*4+3][kk];
            float4 b4 = *(const float4*)&Ws[kk][tx*4];
            acc[0][0] += a0*b4.x; acc[0][1] += a0*b4.y; acc[0][2] += a0*b4.z; acc[0][3] += a0*b4.w;
            acc[1][0] += a1*b4.x; acc[1][1] += a1*b4.y; acc[1][2] += a1*b4.z; acc[1][3] += a1*b4.w;
            acc[2][0] += a2*b4.x; acc[2][1] += a2*b4.y; acc[2][2] += a2*b4.z; acc[2][3] += a2*b4.w;
            acc[3][0] += a3*b4.x; acc[3][1] += a3*b4.y; acc[3][2] += a3*b4.z; acc[3][3] += a3*b4.w;
        }
        __syncthreads();
    }

    #pragma unroll
    for (int i = 0; i < 4; i++)
        #pragma unroll
        for (int j = 0; j < 4; j++)
            O[(size_t)(row0 + ty*4 + i) * HS_ + tx*4 + j] = acc[i][j] * scale;
}

// ---------------------------------------------------------------------------
// Kernel 2: flash attention.  grid = (T/64, H, B), block = 256 (8 warps).
// Each warp handles 8 query rows; each lane owns cols/dims {lane, lane+32}.
// Dynamic SMEM: Qs,Ks,Vt,Ps each [64][68] floats (stride 68 -> 16B-aligned
// float4 + conflict-free strided row access).
// ---------------------------------------------------------------------------
constexpr int FL_LDS  = 68;
constexpr int FL_SMEM = 4 * 64 * FL_LDS * (int)sizeof(float); // 69632 bytes

__global__ __launch_bounds__(256) void flash_kernel()
{
    extern __shared__ float sm[];
    float* Qs = sm;
    float* Ks = sm + 1 * 64 * FL_LDS;
    float* Vt = sm + 2 * 64 * FL_LDS;   // transposed: Vt[d][c] = V[c][d]
    float* Ps = sm + 3 * 64 * FL_LDS;

    const int b    = blockIdx.z;
    const int h    = blockIdx.y;
    const int q0   = blockIdx.x * 64;
    const int tid  = threadIdx.x;
    const int warp = tid >> 5;
    const int lane = tid & 31;
    const int c0   = lane;
    const int c1   = lane + 32;
    const int rowbase = warp * 8;

    const float* Qg = g_Q + ((size_t)(b * H_ + h) * T_ + q0) * HS_;
    const float* Kg = g_K + (size_t)(b * H_ + h) * S_ * HS_;
    const float* Vg = g_V + (size_t)(b * H_ + h) * S_ * HS_;

    // Load Q tile (64x64)
    #pragma unroll
    for (int i = 0; i < 16; i++) {
        int idx = tid + i * 256;
        int r = idx >> 6, c = idx & 63;
        Qs[r * FL_LDS + c] = Qg[r * 64 + c];
    }

    float m_i[8], l_i[8], acc0[8], acc1[8];
    #pragma unroll
    for (int r = 0; r < 8; r++) { m_i[r] = -1e30f; l_i[r] = 0.f; acc0[r] = 0.f; acc1[r] = 0.f; }

    for (int tile = 0; tile < S_ / 64; tile++) {
        __syncthreads();   // previous-iter readers of Ks/Vt done; also covers Q load on iter 0
        #pragma unroll
        for (int i = 0; i < 16; i++) {
            int idx = tid + i * 256;
            int r = idx >> 6, c = idx & 63;
            float kv = Kg[(size_t)(tile * 64 + r) * 64 + c];
            float vv = Vg[(size_t)(tile * 64 + r) * 64 + c];
            Ks[r * FL_LDS + c] = kv;
            Vt[c * FL_LDS + r] = vv;   // transpose on store
        }
        __syncthreads();

        // S = Q @ K^T for this tile: s0 = col c0, s1 = col c1
        float s0[8] = {}, s1[8] = {};
        #pragma unroll
        for (int kb = 0; kb < 16; kb++) {
            float4 k0 = *(const float4*)&Ks[c0 * FL_LDS + kb * 4];
            float4 k1 = *(const float4*)&Ks[c1 * FL_LDS + kb * 4];
            #pragma unroll
            for (int r = 0; r < 8; r++) {
                float4 q = *(const float4*)&Qs[(rowbase + r) * FL_LDS + kb * 4];
                s0[r] += q.x*k0.x + q.y*k0.y + q.z*k0.z + q.w*k0.w;
                s1[r] += q.x*k1.x + q.y*k1.y + q.z*k1.z + q.w*k1.w;
            }
        }

        // Online softmax update
        #pragma unroll
        for (int r = 0; r < 8; r++) {
            float tm = fmaxf(s0[r], s1[r]);
            #pragma unroll
            for (int off = 16; off > 0; off >>= 1)
                tm = fmaxf(tm, __shfl_xor_sync(0xffffffffu, tm, off));
            float mnew = fmaxf(m_i[r], tm);
            float p0 = __expf(s0[r] - mnew);
            float p1 = __expf(s1[r] - mnew);
            float ts = p0 + p1;
            #pragma unroll
            for (int off = 16; off > 0; off >>= 1)
                ts += __shfl_xor_sync(0xffffffffu, ts, off);
            float alpha = __expf(m_i[r] - mnew);
            l_i[r] = l_i[r] * alpha + ts;
            acc0[r] *= alpha;
            acc1[r] *= alpha;
            m_i[r] = mnew;
            Ps[(rowbase + r) * FL_LDS + c0] = p0;
            Ps[(rowbase + r) * FL_LDS + c1] = p1;
        }
        __syncwarp();   // Ps region is warp-private; order writes before reads

        // acc += P @ V   (lane owns output dims c0, c1)
        #pragma unroll
        for (int kb = 0; kb < 16; kb++) {
            float4 v0 = *(const float4*)&Vt[c0 * FL_LDS + kb * 4];
            float4 v1 = *(const float4*)&Vt[c1 * FL_LDS + kb * 4];
            #pragma unroll
            for (int r = 0; r < 8; r++) {
                float4 p = *(const float4*)&Ps[(rowbase + r) * FL_LDS + kb * 4];
                acc0[r] += p.x*v0.x + p.y*v0.y + p.z*v0.z + p.w*v0.w;
                acc1[r] += p.x*v1.x + p.y*v1.y + p.z*v1.z + p.w*v1.w;
            }
        }
    }

    // Epilogue: normalize and store to [B,T,H,HS]
    #pragma unroll
    for (int r = 0; r < 8; r++) {
        float inv = 1.0f / l_i[r];
        int t = q0 + rowbase + r;
        float* o = g_MH + ((size_t)(b * T_ + t) * H_ + h) * HS_;
        o[c0] = acc0[r] * inv;
        o[c1] = acc1[r] * inv;
    }
}

// ---------------------------------------------------------------------------
// Kernel 3: output projection.  C[4096,512] = MH[4096,512] @ Wp[512,512] + bias
// (projection_kernel [H,HS,D] is already row-major [H*HS, D].)
// grid = (B*T/64, D/64), block = 256.
// ---------------------------------------------------------------------------
__global__ __launch_bounds__(256) void out_proj_kernel(
    const float* __restrict__ Wp, const float* __restrict__ bias, float* __restrict__ out)
{
    __shared__ float As[64][33];
    __shared__ float Ws[32][68];

    const int row0 = blockIdx.x * 64;
    const int col0 = blockIdx.y * 64;
    const int tid  = threadIdx.x;
    const int tx   = tid & 15;
    const int ty   = tid >> 4;

    float acc[4][4] = {};

    for (int k0 = 0; k0 < H_ * HS_; k0 += 32) {
        #pragma unroll
        for (int i = 0; i < 8; i++) {
            int idx = tid + i * 256;
            int r = idx >> 5, c = idx & 31;
            As[r][c] = g_MH[(size_t)(row0 + r) * (H_ * HS_) + k0 + c];
        }
        #pragma unroll
        for (int i = 0; i < 8; i++) {
            int idx = tid + i * 256;
            int r = idx >> 6, c = idx & 63;
            Ws[r][c] = Wp[(size_t)(k0 + r) * D_ + col0 + c];
        }
        __syncthreads();

        #pragma unroll
        for (int kk = 0; kk < 32; kk++) {
            float a0 = As[ty*4+0][kk];
            float a1 = As[ty*4+1][kk];
            float a2 = As[ty*4+2][kk];
            float a3 = As[ty*4+3][kk];
            float4 b4 = *(const float4*)&Ws[kk][tx*4];
            acc[0][0] += a0*b4.x; acc[0][1] += a0*b4.y; acc[0][2] += a0*b4.z; acc[0][3] += a0*b4.w;
            acc[1][0] += a1*b4.x; acc[1][1] += a1*b4.y; acc[1][2] += a1*b4.z; acc[1][3] += a1*b4.w;
            acc[2][0] += a2*b4.x; acc[2][1] += a2*b4.y; acc[2][2] += a2*b4.z; acc[2][3] += a2*b4.w;
            acc[3][0] += a3*b4.x; acc[3][1] += a3*b4.y; acc[3][2] += a3*b4.z; acc[3][3] += a3*b4.w;
        }
        __syncthreads();
    }

    #pragma unroll
    for (int i = 0; i < 4; i++) {
        #pragma unroll
        for (int j = 0; j < 4; j++) {
            int col = col0 + tx*4 + j;
            out[(size_t)(row0 + ty*4 + i) * D_ + col] = acc[i][j] + bias[col];
        }
    }
}

// ---------------------------------------------------------------------------
extern "C" void kernel_launch(void* const* d_in, const int* in_sizes, int n_in,
                              void* d_out, int out_size)
{
    const float* query = (const float*)d_in[0];
    const float* key   = (const float*)d_in[1];
    const float* value = (const float*)d_in[2];
    const float* wq    = (const float*)d_in[3];
    const float* wk    = (const float*)d_in[4];
    const float* wv    = (const float*)d_in[5];
    const float* wp    = (const float*)d_in[6];
    const float* bias  = (const float*)d_in[7];
    float* out = (float*)d_out;

    cudaFuncSetAttribute(flash_kernel, cudaFuncAttributeMaxDynamicSharedMemorySize, FL_SMEM);

    qkv_proj_kernel<<<dim3(T_/64, H_, B_*3), 256>>>(query, key, value, wq, wk, wv);
    flash_kernel<<<dim3(T_/64, H_, B_), 256, FL_SMEM>>>();
    out_proj_kernel<<<dim3((B_*T_)/64, D_/64), 256>>>(wp, bias, out);
}

// round 2
// speedup vs baseline: 3.2122x; 3.2122x over previous
#include <cuda_runtime.h>
#include <cuda_bf16.h>

// Problem constants
constexpr int B_  = 2;
constexpr int T_  = 2048;
constexpr int S_  = 2048;
constexpr int D_  = 512;
constexpr int H_  = 8;
constexpr int HS_ = 64;

// Scratch (device globals; no dynamic allocation allowed)
__device__ float g_Q [B_*H_*T_*HS_];   // [B,H,T,HS]  (pre-scaled by 1/sqrt(HS))
__device__ float g_K [B_*H_*S_*HS_];   // [B,H,S,HS]
__device__ float g_V [B_*H_*S_*HS_];   // [B,H,S,HS]
__device__ float g_MH[B_*T_*H_*HS_];   // [B,T,H,HS]

// ---------------------------------------------------------------------------
// tf32 helpers
// ---------------------------------------------------------------------------
__device__ __forceinline__ float to_tf32(float x) {
    asm("cvt.rna.tf32.f32 %0, %0;" : "+f"(x));
    return x;
}

// D += A @ B  with m16n8k8 tf32, fp32 accum (C==D in place)
__device__ __forceinline__ void mma_tf32(float d[4], const unsigned a[4], const unsigned b[2]) {
    asm volatile(
        "mma.sync.aligned.m16n8k8.row.col.f32.tf32.tf32.f32 "
        "{%0,%1,%2,%3}, {%4,%5,%6,%7}, {%8,%9}, {%0,%1,%2,%3};"
        : "+f"(d[0]), "+f"(d[1]), "+f"(d[2]), "+f"(d[3])
        : "r"(a[0]), "r"(a[1]), "r"(a[2]), "r"(a[3]),
          "r"(b[0]), "r"(b[1]));
}

__device__ __forceinline__ unsigned f2u(float x) { return __float_as_uint(x); }

// ---------------------------------------------------------------------------
// Kernel 1: QKV projection (tf32 mma).  Per (b,h,which): O[2048,64] = X @ W[h]
// grid = (T/128, H, 3B), block = 256 (8 warps = 4m x 2n).
// ---------------------------------------------------------------------------
__global__ __launch_bounds__(256) void qkv_mma(
    const float* __restrict__ xq, const float* __restrict__ xk, const float* __restrict__ xv,
    const float* __restrict__ wq, const float* __restrict__ wk, const float* __restrict__ wv)
{
    __shared__ float As[128][36];   // 128 rows x 32 k (+4 pad)
    __shared__ float Bs[32][68];    // 32 k x 64 n (+4 pad)

    const int which = blockIdx.z % 3;
    const int b     = blockIdx.z / 3;
    const int h     = blockIdx.y;
    const int row0  = blockIdx.x * 128;

    const float* X; const float* W; float* O; float scale;
    if (which == 0)      { X = xq; W = wq; O = g_Q; scale = 0.125f; }
    else if (which == 1) { X = xk; W = wk; O = g_K; scale = 1.0f; }
    else                 { X = xv; W = wv; O = g_V; scale = 1.0f; }

    X += (size_t)b * T_ * D_;
    W += (size_t)h * D_ * HS_;
    O += (size_t)(b * H_ + h) * T_ * HS_;

    const int tid  = threadIdx.x;
    const int lane = tid & 31;
    const int w    = tid >> 5;
    const int wm   = w & 3;          // row-warp: 32 rows each
    const int wn   = w >> 2;         // col-warp: 32 cols each
    const int p    = lane >> 2;
    const int q    = lane & 3;

    float C[2][4][4] = {};

    for (int k0 = 0; k0 < D_; k0 += 32) {
        #pragma unroll
        for (int i = 0; i < 4; i++) {
            int idx = tid + i * 256;                 // 1024 float4
            int r = idx >> 3, c = (idx & 7) * 4;
            float4 v = *(const float4*)&X[(size_t)(row0 + r) * D_ + k0 + c];
            As[r][c+0] = to_tf32(v.x); As[r][c+1] = to_tf32(v.y);
            As[r][c+2] = to_tf32(v.z); As[r][c+3] = to_tf32(v.w);
        }
        #pragma unroll
        for (int i = 0; i < 2; i++) {
            int idx = tid + i * 256;                 // 512 float4
            int r = idx >> 4, c = (idx & 15) * 4;
            float4 v = *(const float4*)&W[(size_t)(k0 + r) * HS_ + c];
            Bs[r][c+0] = to_tf32(v.x); Bs[r][c+1] = to_tf32(v.y);
            Bs[r][c+2] = to_tf32(v.z); Bs[r][c+3] = to_tf32(v.w);
        }
        __syncthreads();

        #pragma unroll
        for (int ks = 0; ks < 4; ks++) {
            unsigned af[2][4], bf[4][2];
            #pragma unroll
            for (int mt = 0; mt < 2; mt++) {
                int r = wm*32 + mt*16 + p;
                int c = ks*8 + q;
                af[mt][0] = f2u(As[r  ][c  ]);
                af[mt][1] = f2u(As[r+8][c  ]);
                af[mt][2] = f2u(As[r  ][c+4]);
                af[mt][3] = f2u(As[r+8][c+4]);
            }
            #pragma unroll
            for (int nt = 0; nt < 4; nt++) {
                int r = ks*8 + q;
                int c = wn*32 + nt*8 + p;
                bf[nt][0] = f2u(Bs[r  ][c]);
                bf[nt][1] = f2u(Bs[r+4][c]);
            }
            #pragma unroll
            for (int mt = 0; mt < 2; mt++)
                #pragma unroll
                for (int nt = 0; nt < 4; nt++)
                    mma_tf32(C[mt][nt], af[mt], bf[nt]);
        }
        __syncthreads();
    }

    #pragma unroll
    for (int mt = 0; mt < 2; mt++) {
        int r = row0 + wm*32 + mt*16 + p;
        #pragma unroll
        for (int nt = 0; nt < 4; nt++) {
            int c = wn*32 + nt*8 + 2*q;
            *(float2*)&O[(size_t)r    * HS_ + c] = make_float2(C[mt][nt][0]*scale, C[mt][nt][1]*scale);
            *(float2*)&O[(size_t)(r+8)* HS_ + c] = make_float2(C[mt][nt][2]*scale, C[mt][nt][3]*scale);
        }
    }
}

// ---------------------------------------------------------------------------
// Kernel 2: flash attention with tf32 mma.
// grid = (T/128, H, B), block = 256 (8 warps, warp w owns q rows [16w,16w+16)).
// SMEM: Qs[128][68] (recycled as P buffer), Ks[64][68], Vs[64][68].
// ---------------------------------------------------------------------------
constexpr int FLS     = 68;
constexpr int FL_SMEM = (128 + 64 + 64) * FLS * (int)sizeof(float);   // 69632 B

__global__ __launch_bounds__(256, 2) void flash_mma()
{
    extern __shared__ float sm[];
    float* Qs = sm;                       // 128 x 68 ; becomes Ps after prologue
    float* Ks = sm + 128 * FLS;           // 64 x 68
    float* Vs = sm + 128 * FLS + 64 * FLS;// 64 x 68

    const int b    = blockIdx.z;
    const int h    = blockIdx.y;
    const int q0   = blockIdx.x * 128;
    const int tid  = threadIdx.x;
    const int w    = tid >> 5;
    const int lane = tid & 31;
    const int p    = lane >> 2;
    const int q    = lane & 3;
    const int r0   = w * 16 + p;          // first fragment row within tile

    const float* Qg = g_Q + ((size_t)(b * H_ + h) * T_ + q0) * HS_;
    const float* Kg = g_K + (size_t)(b * H_ + h) * S_ * HS_;
    const float* Vg = g_V + (size_t)(b * H_ + h) * S_ * HS_;

    // Prologue: load Q tile (128x64) into SMEM, then Q fragments into regs.
    #pragma unroll
    for (int i = 0; i < 8; i++) {
        int idx = tid + i * 256;                   // 2048 float4
        int r = idx >> 4, c = (idx & 15) * 4;
        float4 v = *(const float4*)&Qg[(size_t)r * HS_ + c];
        Qs[r*FLS+c+0] = to_tf32(v.x); Qs[r*FLS+c+1] = to_tf32(v.y);
        Qs[r*FLS+c+2] = to_tf32(v.z); Qs[r*FLS+c+3] = to_tf32(v.w);
    }
    __syncthreads();

    unsigned qf[8][4];
    #pragma unroll
    for (int kt = 0; kt < 8; kt++) {
        int c = kt*8 + q;
        qf[kt][0] = f2u(Qs[ r0   *FLS + c  ]);
        qf[kt][1] = f2u(Qs[(r0+8)*FLS + c  ]);
        qf[kt][2] = f2u(Qs[ r0   *FLS + c+4]);
        qf[kt][3] = f2u(Qs[(r0+8)*FLS + c+4]);
    }
    // From here each warp only touches its own 16 rows of Qs (as P buffer).

    float O[8][4] = {};
    float m0 = -1e30f, m1 = -1e30f, l0 = 0.f, l1 = 0.f;

    for (int t = 0; t < S_ / 64; t++) {
        __syncthreads();   // all warps done with previous Ks/Vs
        #pragma unroll
        for (int i = 0; i < 4; i++) {
            int idx = tid + i * 256;               // 1024 float4
            int r = idx >> 4, c = (idx & 15) * 4;
            float4 kv = *(const float4*)&Kg[((size_t)t*64 + r) * HS_ + c];
            float4 vv = *(const float4*)&Vg[((size_t)t*64 + r) * HS_ + c];
            Ks[r*FLS+c+0] = to_tf32(kv.x); Ks[r*FLS+c+1] = to_tf32(kv.y);
            Ks[r*FLS+c+2] = to_tf32(kv.z); Ks[r*FLS+c+3] = to_tf32(kv.w);
            Vs[r*FLS+c+0] = to_tf32(vv.x); Vs[r*FLS+c+1] = to_tf32(vv.y);
            Vs[r*FLS+c+2] = to_tf32(vv.z); Vs[r*FLS+c+3] = to_tf32(vv.w);
        }
        __syncthreads();

        // S[16 x 64] = Q @ K^T  (B fragment: K^T[d][s] = Ks[s][d])
        float Sf[8][4] = {};
        #pragma unroll
        for (int nt = 0; nt < 8; nt++) {
            #pragma unroll
            for (int kt = 0; kt < 8; kt++) {
                unsigned bf[2];
                bf[0] = f2u(Ks[(nt*8+p)*FLS + kt*8 + q    ]);
                bf[1] = f2u(Ks[(nt*8+p)*FLS + kt*8 + q + 4]);
                mma_tf32(Sf[nt], qf[kt], bf);
            }
        }

        // Online softmax (rows r0 and r0+8)
        float tm0 = -1e30f, tm1 = -1e30f;
        #pragma unroll
        for (int nt = 0; nt < 8; nt++) {
            tm0 = fmaxf(tm0, fmaxf(Sf[nt][0], Sf[nt][1]));
            tm1 = fmaxf(tm1, fmaxf(Sf[nt][2], Sf[nt][3]));
        }
        tm0 = fmaxf(tm0, __shfl_xor_sync(0xffffffffu, tm0, 1));
        tm0 = fmaxf(tm0, __shfl_xor_sync(0xffffffffu, tm0, 2));
        tm1 = fmaxf(tm1, __shfl_xor_sync(0xffffffffu, tm1, 1));
        tm1 = fmaxf(tm1, __shfl_xor_sync(0xffffffffu, tm1, 2));
        float mn0 = fmaxf(m0, tm0), mn1 = fmaxf(m1, tm1);
        float a0  = __expf(m0 - mn0), a1 = __expf(m1 - mn1);

        float ts0 = 0.f, ts1 = 0.f;
        #pragma unroll
        for (int nt = 0; nt < 8; nt++) {
            float p00 = __expf(Sf[nt][0] - mn0);
            float p01 = __expf(Sf[nt][1] - mn0);
            float p10 = __expf(Sf[nt][2] - mn1);
            float p11 = __expf(Sf[nt][3] - mn1);
            ts0 += p00 + p01;
            ts1 += p10 + p11;
            *(float2*)&Qs[ r0   *FLS + nt*8 + 2*q] = make_float2(to_tf32(p00), to_tf32(p01));
            *(float2*)&Qs[(r0+8)*FLS + nt*8 + 2*q] = make_float2(to_tf32(p10), to_tf32(p11));
        }
        ts0 += __shfl_xor_sync(0xffffffffu, ts0, 1);
        ts0 += __shfl_xor_sync(0xffffffffu, ts0, 2);
        ts1 += __shfl_xor_sync(0xffffffffu, ts1, 1);
        ts1 += __shfl_xor_sync(0xffffffffu, ts1, 2);
        l0 = l0 * a0 + ts0;
        l1 = l1 * a1 + ts1;
        m0 = mn0; m1 = mn1;

        #pragma unroll
        for (int nt = 0; nt < 8; nt++) {
            O[nt][0] *= a0; O[nt][1] *= a0;
            O[nt][2] *= a1; O[nt][3] *= a1;
        }
        __syncwarp();   // P rows are warp-private; order stores before A-frag loads

        // O += P @ V
        #pragma unroll
        for (int kt = 0; kt < 8; kt++) {
            unsigned af[4];
            af[0] = f2u(Qs[ r0   *FLS + kt*8 + q    ]);
            af[1] = f2u(Qs[(r0+8)*FLS + kt*8 + q    ]);
            af[2] = f2u(Qs[ r0   *FLS + kt*8 + q + 4]);
            af[3] = f2u(Qs[(r0+8)*FLS + kt*8 + q + 4]);
            #pragma unroll
            for (int nt = 0; nt < 8; nt++) {
                unsigned bf[2];
                bf[0] = f2u(Vs[(kt*8 + q    )*FLS + nt*8 + p]);
                bf[1] = f2u(Vs[(kt*8 + q + 4)*FLS + nt*8 + p]);
                mma_tf32(O[nt], af, bf);
            }
        }
    }

    // Epilogue: normalize, store to [B,T,H,HS]
    float inv0 = 1.0f / l0, inv1 = 1.0f / l1;
    int tq = q0 + r0;
    float* o0 = g_MH + ((size_t)(b * T_ + tq    ) * H_ + h) * HS_;
    float* o1 = g_MH + ((size_t)(b * T_ + tq + 8) * H_ + h) * HS_;
    #pragma unroll
    for (int nt = 0; nt < 8; nt++) {
        *(float2*)&o0[nt*8 + 2*q] = make_float2(O[nt][0]*inv0, O[nt][1]*inv0);
        *(float2*)&o1[nt*8 + 2*q] = make_float2(O[nt][2]*inv1, O[nt][3]*inv1);
    }
}

// ---------------------------------------------------------------------------
// Kernel 3: output projection (tf32 mma). out[4096,512] = MH @ Wp + bias.
// grid = (4096/128, 512/64), block = 256 (8 warps = 4m x 2n).
// ---------------------------------------------------------------------------
__global__ __launch_bounds__(256) void out_mma(
    const float* __restrict__ Wp, const float* __restrict__ bias, float* __restrict__ out)
{
    __shared__ float As[128][36];
    __shared__ float Bs[32][68];

    const int row0 = blockIdx.x * 128;
    const int col0 = blockIdx.y * 64;

    const int tid  = threadIdx.x;
    const int lane = tid & 31;
    const int w    = tid >> 5;
    const int wm   = w & 3;
    const int wn   = w >> 2;
    const int p    = lane >> 2;
    const int q    = lane & 3;

    float C[2][4][4] = {};

    for (int k0 = 0; k0 < D_; k0 += 32) {
        #pragma unroll
        for (int i = 0; i < 4; i++) {
            int idx = tid + i * 256;
            int r = idx >> 3, c = (idx & 7) * 4;
            float4 v = *(const float4*)&g_MH[(size_t)(row0 + r) * D_ + k0 + c];
            As[r][c+0] = to_tf32(v.x); As[r][c+1] = to_tf32(v.y);
            As[r][c+2] = to_tf32(v.z); As[r][c+3] = to_tf32(v.w);
        }
        #pragma unroll
        for (int i = 0; i < 2; i++) {
            int idx = tid + i * 256;
            int r = idx >> 4, c = (idx & 15) * 4;
            float4 v = *(const float4*)&Wp[(size_t)(k0 + r) * D_ + col0 + c];
            Bs[r][c+0] = to_tf32(v.x); Bs[r][c+1] = to_tf32(v.y);
            Bs[r][c+2] = to_tf32(v.z); Bs[r][c+3] = to_tf32(v.w);
        }
        __syncthreads();

        #pragma unroll
        for (int ks = 0; ks < 4; ks++) {
            unsigned af[2][4], bf[4][2];
            #pragma unroll
            for (int mt = 0; mt < 2; mt++) {
                int r = wm*32 + mt*16 + p;
                int c = ks*8 + q;
                af[mt][0] = f2u(As[r  ][c  ]);
                af[mt][1] = f2u(As[r+8][c  ]);
                af[mt][2] = f2u(As[r  ][c+4]);
                af[mt][3] = f2u(As[r+8][c+4]);
            }
            #pragma unroll
            for (int nt = 0; nt < 4; nt++) {
                int r = ks*8 + q;
                int c = wn*32 + nt*8 + p;
                bf[nt][0] = f2u(Bs[r  ][c]);
                bf[nt][1] = f2u(Bs[r+4][c]);
            }
            #pragma unroll
            for (int mt = 0; mt < 2; mt++)
                #pragma unroll
                for (int nt = 0; nt < 4; nt++)
                    mma_tf32(C[mt][nt], af[mt], bf[nt]);
        }
        __syncthreads();
    }

    #pragma unroll
    for (int mt = 0; mt < 2; mt++) {
        int r = row0 + wm*32 + mt*16 + p;
        #pragma unroll
        for (int nt = 0; nt < 4; nt++) {
            int c = col0 + wn*32 + nt*8 + 2*q;
            float2 bb = *(const float2*)&bias[c];
            *(float2*)&out[(size_t)r    * D_ + c] = make_float2(C[mt][nt][0]+bb.x, C[mt][nt][1]+bb.y);
            *(float2*)&out[(size_t)(r+8)* D_ + c] = make_float2(C[mt][nt][2]+bb.x, C[mt][nt][3]+bb.y);
        }
    }
}

// ---------------------------------------------------------------------------
extern "C" void kernel_launch(void* const* d_in, const int* in_sizes, int n_in,
                              void* d_out, int out_size)
{
    const float* query = (const float*)d_in[0];
    const float* key   = (const float*)d_in[1];
    const float* value = (const float*)d_in[2];
    const float* wq    = (const float*)d_in[3];
    const float* wk    = (const float*)d_in[4];
    const float* wv    = (const float*)d_in[5];
    const float* wp    = (const float*)d_in[6];
    const float* bias  = (const float*)d_in[7];
    float* out = (float*)d_out;

    cudaFuncSetAttribute(flash_mma, cudaFuncAttributeMaxDynamicSharedMemorySize, FL_SMEM);

    qkv_mma<<<dim3(T_/128, H_, 3*B_), 256>>>(query, key, value, wq, wk, wv);
    flash_mma<<<dim3(T_/128, H_, B_), 256, FL_SMEM>>>();
    out_mma<<<dim3((B_*T_)/128, D_/64), 256>>>(wp, bias, out);
}

// round 4
// speedup vs baseline: 3.4109x; 1.0619x over previous
#include <cuda_runtime.h>
#include <cuda_bf16.h>
#include <cstdint>

// Problem constants
constexpr int B_  = 2;
constexpr int T_  = 2048;
constexpr int S_  = 2048;
constexpr int D_  = 512;
constexpr int H_  = 8;
constexpr int HS_ = 64;

// Scratch (device globals). Q/K/V stored PRE-ROUNDED to tf32 bit patterns.
__device__ float g_Q [B_*H_*T_*HS_];   // [B,H,T,HS]  (scaled by 0.125*log2e, tf32-rounded)
__device__ float g_K [B_*H_*S_*HS_];   // [B,H,S,HS]  (tf32-rounded)
__device__ float g_V [B_*H_*S_*HS_];   // [B,H,S,HS]  (tf32-rounded)
__device__ float g_MH[B_*T_*H_*HS_];   // [B,T,H,HS]

// ---------------------------------------------------------------------------
// helpers
// ---------------------------------------------------------------------------
__device__ __forceinline__ float to_tf32(float x) {
    asm("cvt.rna.tf32.f32 %0, %0;" : "+f"(x));
    return x;
}
__device__ __forceinline__ unsigned f2u(float x) { return __float_as_uint(x); }

__device__ __forceinline__ void mma_tf32(float d[4], const unsigned a[4], const unsigned b[2]) {
    asm volatile(
        "mma.sync.aligned.m16n8k8.row.col.f32.tf32.tf32.f32 "
        "{%0,%1,%2,%3}, {%4,%5,%6,%7}, {%8,%9}, {%0,%1,%2,%3};"
        : "+f"(d[0]), "+f"(d[1]), "+f"(d[2]), "+f"(d[3])
        : "r"(a[0]), "r"(a[1]), "r"(a[2]), "r"(a[3]),
          "r"(b[0]), "r"(b[1]));
}

__device__ __forceinline__ float ex2(float x) {
    float y; asm("ex2.approx.ftz.f32 %0, %1;" : "=f"(y) : "f"(x)); return y;
}

__device__ __forceinline__ void cp16(uint32_t dst, const void* src) {
    asm volatile("cp.async.ca.shared.global [%0], [%1], 16;" :: "r"(dst), "l"(src));
}

constexpr float QSCALE = 0.125f * 1.4426950408889634f;   // 1/sqrt(HS) * log2(e)

// ---------------------------------------------------------------------------
// Kernel 1: QKV projection, head-fused 128x128 tiles, register double-buffer.
// grid = (T/128, (H*HS)/128, 3B), block = 256 (8 warps = 4m x 2n).
// ---------------------------------------------------------------------------
__global__ __launch_bounds__(256, 2) void qkv_mma(
    const float* __restrict__ xq, const float* __restrict__ xk, const float* __restrict__ xv,
    const float* __restrict__ wq, const float* __restrict__ wk, const float* __restrict__ wv)
{
    __shared__ float As[128][36];    // 128 m x 32 k
    __shared__ float Bs[32][132];    // 32 k x 128 n

    const int which = blockIdx.z % 3;
    const int b     = blockIdx.z / 3;
    const int n0    = blockIdx.y * 128;
    const int row0  = blockIdx.x * 128;

    const float* X; const float* W; float* O; float scale;
    if (which == 0)      { X = xq; W = wq; O = g_Q; scale = QSCALE; }
    else if (which == 1) { X = xk; W = wk; O = g_K; scale = 1.0f; }
    else                 { X = xv; W = wv; O = g_V; scale = 1.0f; }

    X += (size_t)b * T_ * D_;

    const int tid  = threadIdx.x;
    const int lane = tid & 31;
    const int w    = tid >> 5;
    const int wm   = w & 3;           // 4 m-warps, 32 rows each
    const int wn   = w >> 2;          // 2 n-warps, 64 cols each (one head per warp)
    const int p    = lane >> 2;
    const int q    = lane & 3;

    float4 aR[4], bR[4];

    // per-thread fixed coordinates for staging
    int ar[4], ac[4], br[4], bc[4];
    const float* bsrc[4];
    #pragma unroll
    for (int i = 0; i < 4; i++) {
        int idx = tid + i * 256;
        ar[i] = idx >> 3;  ac[i] = (idx & 7) * 4;
        int idb = tid + i * 256;
        br[i] = idb >> 5;  bc[i] = (idb & 31) * 4;
        int col = n0 + bc[i];
        bsrc[i] = W + ((size_t)(col >> 6) * D_) * HS_ + (size_t)br[i] * HS_ + (col & 63);
    }

    auto loadA = [&](int k0) {
        #pragma unroll
        for (int i = 0; i < 4; i++)
            aR[i] = *(const float4*)&X[(size_t)(row0 + ar[i]) * D_ + k0 + ac[i]];
    };
    auto loadB = [&](int k0) {
        #pragma unroll
        for (int i = 0; i < 4; i++)
            bR[i] = *(const float4*)(bsrc[i] + (size_t)k0 * HS_);
    };
    auto stage = [&]() {
        #pragma unroll
        for (int i = 0; i < 4; i++) {
            As[ar[i]][ac[i]+0] = to_tf32(aR[i].x); As[ar[i]][ac[i]+1] = to_tf32(aR[i].y);
            As[ar[i]][ac[i]+2] = to_tf32(aR[i].z); As[ar[i]][ac[i]+3] = to_tf32(aR[i].w);
            Bs[br[i]][bc[i]+0] = to_tf32(bR[i].x); Bs[br[i]][bc[i]+1] = to_tf32(bR[i].y);
            Bs[br[i]][bc[i]+2] = to_tf32(bR[i].z); Bs[br[i]][bc[i]+3] = to_tf32(bR[i].w);
        }
    };

    float C[2][8][4] = {};

    loadA(0); loadB(0);
    for (int kc = 0; kc < 16; kc++) {
        stage();
        __syncthreads();
        if (kc < 15) { loadA((kc+1)*32); loadB((kc+1)*32); }   // overlap with mma

        #pragma unroll
        for (int ks = 0; ks < 4; ks++) {
            unsigned af[2][4];
            #pragma unroll
            for (int mt = 0; mt < 2; mt++) {
                int r = wm*32 + mt*16 + p, c = ks*8 + q;
                af[mt][0] = f2u(As[r  ][c  ]);
                af[mt][1] = f2u(As[r+8][c  ]);
                af[mt][2] = f2u(As[r  ][c+4]);
                af[mt][3] = f2u(As[r+8][c+4]);
            }
            #pragma unroll
            for (int nt = 0; nt < 8; nt++) {
                unsigned bf[2];
                bf[0] = f2u(Bs[ks*8+q  ][wn*64 + nt*8 + p]);
                bf[1] = f2u(Bs[ks*8+q+4][wn*64 + nt*8 + p]);
                mma_tf32(C[0][nt], af[0], bf);
                mma_tf32(C[1][nt], af[1], bf);
            }
        }
        __syncthreads();
    }

    // Epilogue: scale + tf32-round, store to [B,H,T,HS]
    const int head = (n0 >> 6) + wn;
    float* Op = O + (size_t)(b * H_ + head) * T_ * HS_;
    #pragma unroll
    for (int mt = 0; mt < 2; mt++) {
        int r = row0 + wm*32 + mt*16 + p;
        #pragma unroll
        for (int nt = 0; nt < 8; nt++) {
            int c = nt*8 + 2*q;
            *(float2*)&Op[(size_t)r    * HS_ + c] =
                make_float2(to_tf32(C[0][nt][0]*scale), to_tf32(C[0][nt][1]*scale));
            *(float2*)&Op[(size_t)(r+8)* HS_ + c] =
                make_float2(to_tf32(C[0][nt][2]*scale), to_tf32(C[0][nt][3]*scale));
        }
        // second m-frag
        #pragma unroll
        for (int nt = 0; nt < 8; nt++) { (void)nt; }
        if (mt == 0) continue;
    }
    // NOTE: loop above only stored mt=0; store mt=1 explicitly (kept separate for clarity)
    {
        int r = row0 + wm*32 + 16 + p;
        #pragma unroll
        for (int nt = 0; nt < 8; nt++) {
            int c = nt*8 + 2*q;
            *(float2*)&Op[(size_t)r    * HS_ + c] =
                make_float2(to_tf32(C[1][nt][0]*scale), to_tf32(C[1][nt][1]*scale));
            *(float2*)&Op[(size_t)(r+8)* HS_ + c] =
                make_float2(to_tf32(C[1][nt][2]*scale), to_tf32(C[1][nt][3]*scale));
        }
    }
}

// ---------------------------------------------------------------------------
// Kernel 2: flash attention, tf32 mma, cp.async double-buffered K/V.
// grid = (T/128, H, B), block = 256. SMEM: Qs[128][68] + 2x(K,V)[64][68].
// ---------------------------------------------------------------------------
constexpr int FLS     = 68;
constexpr int NT      = S_ / 64;
constexpr int FL_SMEM = (128 + 4*64) * FLS * (int)sizeof(float);   // 104448 B

__global__ __launch_bounds__(256, 2) void flash_mma()
{
    extern __shared__ float sm[];
    float* Qs = sm;                                    // 128 x 68 ; reused as P buffer
    const uint32_t smem_u32 = (uint32_t)__cvta_generic_to_shared(sm);

    const int b    = blockIdx.z;
    const int h    = blockIdx.y;
    const int q0   = blockIdx.x * 128;
    const int tid  = threadIdx.x;
    const int w    = tid >> 5;
    const int lane = tid & 31;
    const int p    = lane >> 2;
    const int q    = lane & 3;
    const int r0   = w * 16 + p;

    const float* Qg = g_Q + ((size_t)(b * H_ + h) * T_ + q0) * HS_;
    const float* Kg = g_K + (size_t)(b * H_ + h) * S_ * HS_;
    const float* Vg = g_V + (size_t)(b * H_ + h) * S_ * HS_;

    // prologue: Q tile via cp.async (group 0)
    #pragma unroll
    for (int i = 0; i < 8; i++) {
        int idx = tid + i * 256;
        int r = idx >> 4, c = (idx & 15) * 4;
        cp16(smem_u32 + (uint32_t)((r*FLS + c)*4), Qg + (size_t)r*HS_ + c);
    }
    asm volatile("cp.async.commit_group;");

    auto issue_tile = [&](int t, int s) {
        const float* Kp = Kg + (size_t)t * 64 * HS_;
        const float* Vp = Vg + (size_t)t * 64 * HS_;
        const uint32_t kbase = smem_u32 + (uint32_t)((128 + s*128) * FLS * 4);
        const uint32_t vbase = kbase + (uint32_t)(64 * FLS * 4);
        #pragma unroll
        for (int i = 0; i < 4; i++) {
            int idx = tid + i * 256;
            int r = idx >> 4, c = (idx & 15) * 4;
            uint32_t doff = (uint32_t)((r*FLS + c)*4);
            cp16(kbase + doff, Kp + (size_t)r*HS_ + c);
            cp16(vbase + doff, Vp + (size_t)r*HS_ + c);
        }
        asm volatile("cp.async.commit_group;");
    };

    issue_tile(0, 0);                                  // group 1
    asm volatile("cp.async.wait_group 1;");            // Q ready
    __syncthreads();

    // Q fragments -> registers (reused over all KV tiles)
    unsigned qf[8][4];
    #pragma unroll
    for (int kt = 0; kt < 8; kt++) {
        int c = kt*8 + q;
        qf[kt][0] = f2u(Qs[ r0   *FLS + c  ]);
        qf[kt][1] = f2u(Qs[(r0+8)*FLS + c  ]);
        qf[kt][2] = f2u(Qs[ r0   *FLS + c+4]);
        qf[kt][3] = f2u(Qs[(r0+8)*FLS + c+4]);
    }

    float O[8][4] = {};
    float m0 = -1e30f, m1 = -1e30f, l0 = 0.f, l1 = 0.f;

    for (int t = 0; t < NT; t++) {
        if (t + 1 < NT) {
            issue_tile(t + 1, (t + 1) & 1);
            asm volatile("cp.async.wait_group 1;");    // tile t complete
        } else {
            asm volatile("cp.async.wait_group 0;");
        }
        __syncthreads();

        const float* Ks = sm + (128 + (t & 1) * 128) * FLS;
        const float* Vs = Ks + 64 * FLS;

        // S[16x64] = Q @ K^T
        float Sf[8][4] = {};
        #pragma unroll
        for (int nt = 0; nt < 8; nt++) {
            #pragma unroll
            for (int kt = 0; kt < 8; kt++) {
                unsigned bf[2];
                bf[0] = f2u(Ks[(nt*8+p)*FLS + kt*8 + q    ]);
                bf[1] = f2u(Ks[(nt*8+p)*FLS + kt*8 + q + 4]);
                mma_tf32(Sf[nt], qf[kt], bf);
            }
        }

        // online softmax (base-2 domain; Q pre-scaled by log2e)
        float tm0 = -1e30f, tm1 = -1e30f;
        #pragma unroll
        for (int nt = 0; nt < 8; nt++) {
            tm0 = fmaxf(tm0, fmaxf(Sf[nt][0], Sf[nt][1]));
            tm1 = fmaxf(tm1, fmaxf(Sf[nt][2], Sf[nt][3]));
        }
        tm0 = fmaxf(tm0, __shfl_xor_sync(0xffffffffu, tm0, 1));
        tm0 = fmaxf(tm0, __shfl_xor_sync(0xffffffffu, tm0, 2));
        tm1 = fmaxf(tm1, __shfl_xor_sync(0xffffffffu, tm1, 1));
        tm1 = fmaxf(tm1, __shfl_xor_sync(0xffffffffu, tm1, 2));
        float mn0 = fmaxf(m0, tm0), mn1 = fmaxf(m1, tm1);
        float a0  = ex2(m0 - mn0), a1 = ex2(m1 - mn1);

        float ts0 = 0.f, ts1 = 0.f;
        #pragma unroll
        for (int nt = 0; nt < 8; nt++) {
            float p00 = ex2(Sf[nt][0] - mn0);
            float p01 = ex2(Sf[nt][1] - mn0);
            float p10 = ex2(Sf[nt][2] - mn1);
            float p11 = ex2(Sf[nt][3] - mn1);
            ts0 += p00 + p01;
            ts1 += p10 + p11;
            *(float2*)&Qs[ r0   *FLS + nt*8 + 2*q] = make_float2(to_tf32(p00), to_tf32(p01));
            *(float2*)&Qs[(r0+8)*FLS + nt*8 + 2*q] = make_float2(to_tf32(p10), to_tf32(p11));
        }
        ts0 += __shfl_xor_sync(0xffffffffu, ts0, 1);
        ts0 += __shfl_xor_sync(0xffffffffu, ts0, 2);
        ts1 += __shfl_xor_sync(0xffffffffu, ts1, 1);
        ts1 += __shfl_xor_sync(0xffffffffu, ts1, 2);
        l0 = l0 * a0 + ts0;
        l1 = l1 * a1 + ts1;
        m0 = mn0; m1 = mn1;

        #pragma unroll
        for (int nt = 0; nt < 8; nt++) {
            O[nt][0] *= a0; O[nt][1] *= a0;
            O[nt][2] *= a1; O[nt][3] *= a1;
        }
        __syncwarp();   // P rows are warp-private

        // O += P @ V
        #pragma unroll
        for (int kt = 0; kt < 8; kt++) {
            unsigned af[4];
            af[0] = f2u(Qs[ r0   *FLS + kt*8 + q    ]);
            af[1] = f2u(Qs[(r0+8)*FLS + kt*8 + q    ]);
            af[2] = f2u(Qs[ r0   *FLS + kt*8 + q + 4]);
            af[3] = f2u(Qs[(r0+8)*FLS + kt*8 + q + 4]);
            #pragma unroll
            for (int nt = 0; nt < 8; nt++) {
                unsigned bf[2];
                bf[0] = f2u(Vs[(kt*8 + q    )*FLS + nt*8 + p]);
                bf[1] = f2u(Vs[(kt*8 + q + 4)*FLS + nt*8 + p]);
                mma_tf32(O[nt], af, bf);
            }
        }
        __syncthreads();   // all warps done with this stage before it is refilled
    }

    // epilogue
    float inv0 = 1.0f / l0, inv1 = 1.0f / l1;
    int tq = q0 + r0;
    float* o0 = g_MH + ((size_t)(b * T_ + tq    ) * H_ + h) * HS_;
    float* o1 = g_MH + ((size_t)(b * T_ + tq + 8) * H_ + h) * HS_;
    #pragma unroll
    for (int nt = 0; nt < 8; nt++) {
        *(float2*)&o0[nt*8 + 2*q] = make_float2(O[nt][0]*inv0, O[nt][1]*inv0);
        *(float2*)&o1[nt*8 + 2*q] = make_float2(O[nt][2]*inv1, O[nt][3]*inv1);
    }
}

// ---------------------------------------------------------------------------
// Kernel 3: output projection, 128x128 tiles. out[4096,512] = MH @ Wp + bias.
// grid = (4096/128, 512/128), block = 256.
// ---------------------------------------------------------------------------
__global__ __launch_bounds__(256, 2) void out_mma(
    const float* __restrict__ Wp, const float* __restrict__ bias, float* __restrict__ out)
{
    __shared__ float As[128][36];
    __shared__ float Bs[32][132];

    const int n0   = blockIdx.y * 128;
    const int row0 = blockIdx.x * 128;

    const int tid  = threadIdx.x;
    const int lane = tid & 31;
    const int w    = tid >> 5;
    const int wm   = w & 3;
    const int wn   = w >> 2;
    const int p    = lane >> 2;
    const int q    = lane & 3;

    float4 aR[4], bR[4];
    int ar[4], ac[4], br[4], bc[4];
    #pragma unroll
    for (int i = 0; i < 4; i++) {
        int idx = tid + i * 256;
        ar[i] = idx >> 3;  ac[i] = (idx & 7) * 4;
        br[i] = idx >> 5;  bc[i] = (idx & 31) * 4;
    }

    auto loadA = [&](int k0) {
        #pragma unroll
        for (int i = 0; i < 4; i++)
            aR[i] = *(const float4*)&g_MH[(size_t)(row0 + ar[i]) * D_ + k0 + ac[i]];
    };
    auto loadB = [&](int k0) {
        #pragma unroll
        for (int i = 0; i < 4; i++)
            bR[i] = *(const float4*)&Wp[(size_t)(k0 + br[i]) * D_ + n0 + bc[i]];
    };
    auto stage = [&]() {
        #pragma unroll
        for (int i = 0; i < 4; i++) {
            As[ar[i]][ac[i]+0] = to_tf32(aR[i].x); As[ar[i]][ac[i]+1] = to_tf32(aR[i].y);
            As[ar[i]][ac[i]+2] = to_tf32(aR[i].z); As[ar[i]][ac[i]+3] = to_tf32(aR[i].w);
            Bs[br[i]][bc[i]+0] = to_tf32(bR[i].x); Bs[br[i]][bc[i]+1] = to_tf32(bR[i].y);
            Bs[br[i]][bc[i]+2] = to_tf32(bR[i].z); Bs[br[i]][bc[i]+3] = to_tf32(bR[i].w);
        }
    };

    float C[2][8][4] = {};

    loadA(0); loadB(0);
    for (int kc = 0; kc < 16; kc++) {
        stage();
        __syncthreads();
        if (kc < 15) { loadA((kc+1)*32); loadB((kc+1)*32); }

        #pragma unroll
        for (int ks = 0; ks < 4; ks++) {
            unsigned af[2][4];
            #pragma unroll
            for (int mt = 0; mt < 2; mt++) {
                int r = wm*32 + mt*16 + p, c = ks*8 + q;
                af[mt][0] = f2u(As[r  ][c  ]);
                af[mt][1] = f2u(As[r+8][c  ]);
                af[mt][2] = f2u(As[r  ][c+4]);
                af[mt][3] = f2u(As[r+8][c+4]);
            }
            #pragma unroll
            for (int nt = 0; nt < 8; nt++) {
                unsigned bf[2];
                bf[0] = f2u(Bs[ks*8+q  ][wn*64 + nt*8 + p]);
                bf[1] = f2u(Bs[ks*8+q+4][wn*64 + nt*8 + p]);
                mma_tf32(C[0][nt], af[0], bf);
                mma_tf32(C[1][nt], af[1], bf);
            }
        }
        __syncthreads();
    }

    #pragma unroll
    for (int mt = 0; mt < 2; mt++) {
        int r = row0 + wm*32 + mt*16 + p;
        #pragma unroll
        for (int nt = 0; nt < 8; nt++) {
            int c = n0 + wn*64 + nt*8 + 2*q;
            float2 bb = *(const float2*)&bias[c];
            *(float2*)&out[(size_t)r    * D_ + c] = make_float2(C[mt][nt][0]+bb.x, C[mt][nt][1]+bb.y);
            *(float2*)&out[(size_t)(r+8)* D_ + c] = make_float2(C[mt][nt][2]+bb.x, C[mt][nt][3]+bb.y);
        }
    }
}

// ---------------------------------------------------------------------------
extern "C" void kernel_launch(void* const* d_in, const int* in_sizes, int n_in,
                              void* d_out, int out_size)
{
    const float* query = (const float*)d_in[0];
    const float* key   = (const float*)d_in[1];
    const float* value = (const float*)d_in[2];
    const float* wq    = (const float*)d_in[3];
    const float* wk    = (const float*)d_in[4];
    const float* wv    = (const float*)d_in[5];
    const float* wp    = (const float*)d_in[6];
    const float* bias  = (const float*)d_in[7];
    float* out = (float*)d_out;

    cudaFuncSetAttribute(flash_mma, cudaFuncAttributeMaxDynamicSharedMemorySize, FL_SMEM);

    qkv_mma<<<dim3(T_/128, (H_*HS_)/128, 3*B_), 256>>>(query, key, value, wq, wk, wv);
    flash_mma<<<dim3(T_/128, H_, B_), 256, FL_SMEM>>>();
    out_mma<<<dim3((B_*T_)/128, D_/128), 256>>>(wp, bias, out);
}

// round 5
// speedup vs baseline: 3.5148x; 1.0304x over previous
#include <cuda_runtime.h>
#include <cuda_bf16.h>
#include <cstdint>

// Problem constants
constexpr int B_  = 2;
constexpr int T_  = 2048;
constexpr int S_  = 2048;
constexpr int D_  = 512;
constexpr int H_  = 8;
constexpr int HS_ = 64;

// Scratch (device globals). Q/K/V stored PRE-ROUNDED to tf32 bit patterns.
__device__ float g_Q [B_*H_*T_*HS_];   // [B,H,T,HS]  (scaled by 0.125*log2e, tf32-rounded)
__device__ float g_K [B_*H_*S_*HS_];   // [B,H,S,HS]  (tf32-rounded)
__device__ float g_V [B_*H_*S_*HS_];   // [B,H,S,HS]  (tf32-rounded)
__device__ float g_MH[B_*T_*H_*HS_];   // [B,T,H,HS]

// ---------------------------------------------------------------------------
// helpers
// ---------------------------------------------------------------------------
__device__ __forceinline__ float to_tf32(float x) {
    asm("cvt.rna.tf32.f32 %0, %0;" : "+f"(x));
    return x;
}
__device__ __forceinline__ unsigned f2u(float x) { return __float_as_uint(x); }
__device__ __forceinline__ unsigned frag(float x) { return f2u(to_tf32(x)); }

__device__ __forceinline__ void mma_tf32(float d[4], const unsigned a[4], const unsigned b[2]) {
    asm volatile(
        "mma.sync.aligned.m16n8k8.row.col.f32.tf32.tf32.f32 "
        "{%0,%1,%2,%3}, {%4,%5,%6,%7}, {%8,%9}, {%0,%1,%2,%3};"
        : "+f"(d[0]), "+f"(d[1]), "+f"(d[2]), "+f"(d[3])
        : "r"(a[0]), "r"(a[1]), "r"(a[2]), "r"(a[3]),
          "r"(b[0]), "r"(b[1]));
}

__device__ __forceinline__ float ex2(float x) {
    float y; asm("ex2.approx.ftz.f32 %0, %1;" : "=f"(y) : "f"(x)); return y;
}

__device__ __forceinline__ void cp16(uint32_t dst, const void* src) {
    asm volatile("cp.async.ca.shared.global [%0], [%1], 16;" :: "r"(dst), "l"(src));
}
#define CP_COMMIT()  asm volatile("cp.async.commit_group;")
#define CP_WAIT(n)   asm volatile("cp.async.wait_group %0;" :: "n"(n))

constexpr float QSCALE = 0.125f * 1.4426950408889634f;   // 1/sqrt(HS) * log2(e)

// ---------------------------------------------------------------------------
// Kernel 1: QKV projection. 128x128 tile (2 heads), 3-stage cp.async pipeline.
// grid = (T/128, (H*HS)/128, 3B), block = 256 (8 warps = 4m x 2n).
// ---------------------------------------------------------------------------
constexpr int QST  = 3;                     // stages
constexpr int QA_S = 128 * 36;              // A stage floats
constexpr int QB_S = 32 * 132;              // B stage floats
constexpr int Q_SMEM = QST * (QA_S + QB_S) * 4;   // 105984 B

__global__ __launch_bounds__(256, 2) void qkv_mma(
    const float* __restrict__ xq, const float* __restrict__ xk, const float* __restrict__ xv,
    const float* __restrict__ wq, const float* __restrict__ wk, const float* __restrict__ wv)
{
    extern __shared__ float smp[];
    float* Abase = smp;                     // [QST][128][36]
    float* Bbase = smp + QST * QA_S;        // [QST][32][132]
    const uint32_t smem_u32 = (uint32_t)__cvta_generic_to_shared(smp);

    const int which = blockIdx.z % 3;
    const int b     = blockIdx.z / 3;
    const int n0    = blockIdx.y * 128;
    const int row0  = blockIdx.x * 128;

    const float* X; const float* W; float* O; float scale;
    if (which == 0)      { X = xq; W = wq; O = g_Q; scale = QSCALE; }
    else if (which == 1) { X = xk; W = wk; O = g_K; scale = 1.0f; }
    else                 { X = xv; W = wv; O = g_V; scale = 1.0f; }

    X += (size_t)b * T_ * D_;

    const int tid  = threadIdx.x;
    const int lane = tid & 31;
    const int w    = tid >> 5;
    const int wm   = w & 3;
    const int wn   = w >> 2;
    const int p    = lane >> 2;
    const int q    = lane & 3;

    // copy-coordinate precompute
    int ar[4], ac[4], br[4], bc[4];
    const float* bsrc[4];
    #pragma unroll
    for (int i = 0; i < 4; i++) {
        int idx = tid + i * 256;                 // 1024 A chunks of 16B
        ar[i] = idx >> 3;  ac[i] = (idx & 7) * 4;
        br[i] = idx >> 5;  bc[i] = (idx & 31) * 4;   // 1024 B chunks
        int col = n0 + bc[i];
        bsrc[i] = W + (size_t)(col >> 6) * D_ * HS_ + (size_t)br[i] * HS_ + (col & 63);
    }

    auto issue = [&](int kc) {
        int s = kc % QST;
        int k0 = kc * 32;
        uint32_t ab = smem_u32 + (uint32_t)(s * QA_S * 4);
        uint32_t bb = smem_u32 + (uint32_t)((QST * QA_S + s * QB_S) * 4);
        #pragma unroll
        for (int i = 0; i < 4; i++) {
            cp16(ab + (uint32_t)((ar[i]*36 + ac[i])*4), X + (size_t)(row0 + ar[i]) * D_ + k0 + ac[i]);
            cp16(bb + (uint32_t)((br[i]*132 + bc[i])*4), bsrc[i] + (size_t)k0 * HS_);
        }
    };

    // prologue: stages 0..QST-2
    #pragma unroll
    for (int kc = 0; kc < QST - 1; kc++) { issue(kc); CP_COMMIT(); }

    float C[2][8][4] = {};

    for (int kc = 0; kc < 16; kc++) {
        CP_WAIT(QST - 2);
        __syncthreads();

        if (kc + QST - 1 < 16) issue(kc + QST - 1);
        CP_COMMIT();

        const float* As = Abase + (kc % QST) * QA_S;   // [128][36]
        const float* Bs = Bbase + (kc % QST) * QB_S;   // [32][132]

        #pragma unroll
        for (int ks = 0; ks < 4; ks++) {
            unsigned af[2][4];
            #pragma unroll
            for (int mt = 0; mt < 2; mt++) {
                int r = wm*32 + mt*16 + p, c = ks*8 + q;
                af[mt][0] = frag(As[ r    *36 + c  ]);
                af[mt][1] = frag(As[(r+8) *36 + c  ]);
                af[mt][2] = frag(As[ r    *36 + c+4]);
                af[mt][3] = frag(As[(r+8) *36 + c+4]);
            }
            #pragma unroll
            for (int nt = 0; nt < 8; nt++) {
                unsigned bf[2];
                bf[0] = frag(Bs[(ks*8+q  )*132 + wn*64 + nt*8 + p]);
                bf[1] = frag(Bs[(ks*8+q+4)*132 + wn*64 + nt*8 + p]);
                mma_tf32(C[0][nt], af[0], bf);
                mma_tf32(C[1][nt], af[1], bf);
            }
        }
    }

    // Epilogue: scale + tf32-round, store to [B,H,T,HS]
    const int head = (n0 >> 6) + wn;
    float* Op = O + (size_t)(b * H_ + head) * T_ * HS_;
    #pragma unroll
    for (int mt = 0; mt < 2; mt++) {
        int r = row0 + wm*32 + mt*16 + p;
        #pragma unroll
        for (int nt = 0; nt < 8; nt++) {
            int c = nt*8 + 2*q;
            *(float2*)&Op[(size_t)r    * HS_ + c] =
                make_float2(to_tf32(C[mt][nt][0]*scale), to_tf32(C[mt][nt][1]*scale));
            *(float2*)&Op[(size_t)(r+8)* HS_ + c] =
                make_float2(to_tf32(C[mt][nt][2]*scale), to_tf32(C[mt][nt][3]*scale));
        }
    }
}

// ---------------------------------------------------------------------------
// Kernel 2: flash attention, tf32 mma, cp.async double-buffered K/V.
// grid = (T/128, H, B), block = 256. SMEM: Qs[128][68] + 2x(K,V)[64][68].
// ---------------------------------------------------------------------------
constexpr int FLS     = 68;
constexpr int NT      = S_ / 64;
constexpr int FL_SMEM = (128 + 4*64) * FLS * (int)sizeof(float);   // 104448 B

__global__ __launch_bounds__(256, 2) void flash_mma()
{
    extern __shared__ float sm[];
    float* Qs = sm;                                    // 128 x 68 ; reused as P buffer
    const uint32_t smem_u32 = (uint32_t)__cvta_generic_to_shared(sm);

    const int b    = blockIdx.z;
    const int h    = blockIdx.y;
    const int q0   = blockIdx.x * 128;
    const int tid  = threadIdx.x;
    const int w    = tid >> 5;
    const int lane = tid & 31;
    const int p    = lane >> 2;
    const int q    = lane & 3;
    const int r0   = w * 16 + p;

    const float* Qg = g_Q + ((size_t)(b * H_ + h) * T_ + q0) * HS_;
    const float* Kg = g_K + (size_t)(b * H_ + h) * S_ * HS_;
    const float* Vg = g_V + (size_t)(b * H_ + h) * S_ * HS_;

    // prologue: Q tile via cp.async (group 0)
    #pragma unroll
    for (int i = 0; i < 8; i++) {
        int idx = tid + i * 256;
        int r = idx >> 4, c = (idx & 15) * 4;
        cp16(smem_u32 + (uint32_t)((r*FLS + c)*4), Qg + (size_t)r*HS_ + c);
    }
    CP_COMMIT();

    auto issue_tile = [&](int t, int s) {
        const float* Kp = Kg + (size_t)t * 64 * HS_;
        const float* Vp = Vg + (size_t)t * 64 * HS_;
        const uint32_t kbase = smem_u32 + (uint32_t)((128 + s*128) * FLS * 4);
        const uint32_t vbase = kbase + (uint32_t)(64 * FLS * 4);
        #pragma unroll
        for (int i = 0; i < 4; i++) {
            int idx = tid + i * 256;
            int r = idx >> 4, c = (idx & 15) * 4;
            uint32_t doff = (uint32_t)((r*FLS + c)*4);
            cp16(kbase + doff, Kp + (size_t)r*HS_ + c);
            cp16(vbase + doff, Vp + (size_t)r*HS_ + c);
        }
        CP_COMMIT();
    };

    issue_tile(0, 0);                                  // group 1
    CP_WAIT(1);                                        // Q ready
    __syncthreads();

    // Q fragments -> registers (reused over all KV tiles)
    unsigned qf[8][4];
    #pragma unroll
    for (int kt = 0; kt < 8; kt++) {
        int c = kt*8 + q;
        qf[kt][0] = f2u(Qs[ r0   *FLS + c  ]);
        qf[kt][1] = f2u(Qs[(r0+8)*FLS + c  ]);
        qf[kt][2] = f2u(Qs[ r0   *FLS + c+4]);
        qf[kt][3] = f2u(Qs[(r0+8)*FLS + c+4]);
    }

    float O[8][4] = {};
    float m0 = -1e30f, m1 = -1e30f, l0 = 0.f, l1 = 0.f;

    for (int t = 0; t < NT; t++) {
        if (t + 1 < NT) {
            issue_tile(t + 1, (t + 1) & 1);
            CP_WAIT(1);                                // tile t complete
        } else {
            CP_WAIT(0);
        }
        __syncthreads();

        const float* Ks = sm + (128 + (t & 1) * 128) * FLS;
        const float* Vs = Ks + 64 * FLS;

        // S[16x64] = Q @ K^T
        float Sf[8][4] = {};
        #pragma unroll
        for (int nt = 0; nt < 8; nt++) {
            #pragma unroll
            for (int kt = 0; kt < 8; kt++) {
                unsigned bf[2];
                bf[0] = f2u(Ks[(nt*8+p)*FLS + kt*8 + q    ]);
                bf[1] = f2u(Ks[(nt*8+p)*FLS + kt*8 + q + 4]);
                mma_tf32(Sf[nt], qf[kt], bf);
            }
        }

        // online softmax (base-2 domain; Q pre-scaled by log2e)
        float tm0 = -1e30f, tm1 = -1e30f;
        #pragma unroll
        for (int nt = 0; nt < 8; nt++) {
            tm0 = fmaxf(tm0, fmaxf(Sf[nt][0], Sf[nt][1]));
            tm1 = fmaxf(tm1, fmaxf(Sf[nt][2], Sf[nt][3]));
        }
        tm0 = fmaxf(tm0, __shfl_xor_sync(0xffffffffu, tm0, 1));
        tm0 = fmaxf(tm0, __shfl_xor_sync(0xffffffffu, tm0, 2));
        tm1 = fmaxf(tm1, __shfl_xor_sync(0xffffffffu, tm1, 1));
        tm1 = fmaxf(tm1, __shfl_xor_sync(0xffffffffu, tm1, 2));
        float mn0 = fmaxf(m0, tm0), mn1 = fmaxf(m1, tm1);
        float a0  = ex2(m0 - mn0), a1 = ex2(m1 - mn1);

        float ts0 = 0.f, ts1 = 0.f;
        #pragma unroll
        for (int nt = 0; nt < 8; nt++) {
            float p00 = ex2(Sf[nt][0] - mn0);
            float p01 = ex2(Sf[nt][1] - mn0);
            float p10 = ex2(Sf[nt][2] - mn1);
            float p11 = ex2(Sf[nt][3] - mn1);
            ts0 += p00 + p01;
            ts1 += p10 + p11;
            *(float2*)&Qs[ r0   *FLS + nt*8 + 2*q] = make_float2(to_tf32(p00), to_tf32(p01));
            *(float2*)&Qs[(r0+8)*FLS + nt*8 + 2*q] = make_float2(to_tf32(p10), to_tf32(p11));
        }
        ts0 += __shfl_xor_sync(0xffffffffu, ts0, 1);
        ts0 += __shfl_xor_sync(0xffffffffu, ts0, 2);
        ts1 += __shfl_xor_sync(0xffffffffu, ts1, 1);
        ts1 += __shfl_xor_sync(0xffffffffu, ts1, 2);
        l0 = l0 * a0 + ts0;
        l1 = l1 * a1 + ts1;
        m0 = mn0; m1 = mn1;

        #pragma unroll
        for (int nt = 0; nt < 8; nt++) {
            O[nt][0] *= a0; O[nt][1] *= a0;
            O[nt][2] *= a1; O[nt][3] *= a1;
        }
        __syncwarp();   // P rows are warp-private

        // O += P @ V
        #pragma unroll
        for (int kt = 0; kt < 8; kt++) {
            unsigned af[4];
            af[0] = f2u(Qs[ r0   *FLS + kt*8 + q    ]);
            af[1] = f2u(Qs[(r0+8)*FLS + kt*8 + q    ]);
            af[2] = f2u(Qs[ r0   *FLS + kt*8 + q + 4]);
            af[3] = f2u(Qs[(r0+8)*FLS + kt*8 + q + 4]);
            #pragma unroll
            for (int nt = 0; nt < 8; nt++) {
                unsigned bf[2];
                bf[0] = f2u(Vs[(kt*8 + q    )*FLS + nt*8 + p]);
                bf[1] = f2u(Vs[(kt*8 + q + 4)*FLS + nt*8 + p]);
                mma_tf32(O[nt], af, bf);
            }
        }
        __syncthreads();   // all warps done with this stage before it is refilled
    }

    // epilogue
    float inv0 = 1.0f / l0, inv1 = 1.0f / l1;
    int tq = q0 + r0;
    float* o0 = g_MH + ((size_t)(b * T_ + tq    ) * H_ + h) * HS_;
    float* o1 = g_MH + ((size_t)(b * T_ + tq + 8) * H_ + h) * HS_;
    #pragma unroll
    for (int nt = 0; nt < 8; nt++) {
        *(float2*)&o0[nt*8 + 2*q] = make_float2(O[nt][0]*inv0, O[nt][1]*inv0);
        *(float2*)&o1[nt*8 + 2*q] = make_float2(O[nt][2]*inv1, O[nt][3]*inv1);
    }
}

// ---------------------------------------------------------------------------
// Kernel 3: output projection, 128x64 tiles, 3-stage cp.async pipeline.
// grid = (4096/128, 512/64), block = 256 (8 warps = 4m x 2n, 32 cols/warp).
// ---------------------------------------------------------------------------
constexpr int OA_S = 128 * 36;
constexpr int OB_S = 32 * 68;
constexpr int O_SMEM = QST * (OA_S + OB_S) * 4;   // 81408 B

__global__ __launch_bounds__(256, 2) void out_mma(
    const float* __restrict__ Wp, const float* __restrict__ bias, float* __restrict__ out)
{
    extern __shared__ float smp[];
    float* Abase = smp;                      // [QST][128][36]
    float* Bbase = smp + QST * OA_S;         // [QST][32][68]
    const uint32_t smem_u32 = (uint32_t)__cvta_generic_to_shared(smp);

    const int n0   = blockIdx.y * 64;
    const int row0 = blockIdx.x * 128;

    const int tid  = threadIdx.x;
    const int lane = tid & 31;
    const int w    = tid >> 5;
    const int wm   = w & 3;
    const int wn   = w >> 2;
    const int p    = lane >> 2;
    const int q    = lane & 3;

    int ar[4], ac[4];
    #pragma unroll
    for (int i = 0; i < 4; i++) {
        int idx = tid + i * 256;
        ar[i] = idx >> 3;  ac[i] = (idx & 7) * 4;
    }
    const int br = tid >> 4, bc = (tid & 15) * 4;   // 512 B-chunks, 2 per thread

    auto issue = [&](int kc) {
        int s = kc % QST;
        int k0 = kc * 32;
        uint32_t ab = smem_u32 + (uint32_t)(s * OA_S * 4);
        uint32_t bb = smem_u32 + (uint32_t)((QST * OA_S + s * OB_S) * 4);
        #pragma unroll
        for (int i = 0; i < 4; i++)
            cp16(ab + (uint32_t)((ar[i]*36 + ac[i])*4), g_MH + (size_t)(row0 + ar[i]) * D_ + k0 + ac[i]);
        #pragma unroll
        for (int i = 0; i < 2; i++) {
            int r = br + i*16;
            cp16(bb + (uint32_t)((r*68 + bc)*4), Wp + (size_t)(k0 + r) * D_ + n0 + bc);
        }
    };

    #pragma unroll
    for (int kc = 0; kc < QST - 1; kc++) { issue(kc); CP_COMMIT(); }

    float C[2][4][4] = {};

    for (int kc = 0; kc < 16; kc++) {
        CP_WAIT(QST - 2);
        __syncthreads();

        if (kc + QST - 1 < 16) issue(kc + QST - 1);
        CP_COMMIT();

        const float* As = Abase + (kc % QST) * OA_S;
        const float* Bs = Bbase + (kc % QST) * OB_S;

        #pragma unroll
        for (int ks = 0; ks < 4; ks++) {
            unsigned af[2][4];
            #pragma unroll
            for (int mt = 0; mt < 2; mt++) {
                int r = wm*32 + mt*16 + p, c = ks*8 + q;
                af[mt][0] = frag(As[ r    *36 + c  ]);
                af[mt][1] = frag(As[(r+8) *36 + c  ]);
                af[mt][2] = frag(As[ r    *36 + c+4]);
                af[mt][3] = frag(As[(r+8) *36 + c+4]);
            }
            #pragma unroll
            for (int nt = 0; nt < 4; nt++) {
                unsigned bf[2];
                bf[0] = frag(Bs[(ks*8+q  )*68 + wn*32 + nt*8 + p]);
                bf[1] = frag(Bs[(ks*8+q+4)*68 + wn*32 + nt*8 + p]);
                mma_tf32(C[0][nt], af[0], bf);
                mma_tf32(C[1][nt], af[1], bf);
            }
        }
    }

    #pragma unroll
    for (int mt = 0; mt < 2; mt++) {
        int r = row0 + wm*32 + mt*16 + p;
        #pragma unroll
        for (int nt = 0; nt < 4; nt++) {
            int c = n0 + wn*32 + nt*8 + 2*q;
            float2 bb = *(const float2*)&bias[c];
            *(float2*)&out[(size_t)r    * D_ + c] = make_float2(C[mt][nt][0]+bb.x, C[mt][nt][1]+bb.y);
            *(float2*)&out[(size_t)(r+8)* D_ + c] = make_float2(C[mt][nt][2]+bb.x, C[mt][nt][3]+bb.y);
        }
    }
}

// ---------------------------------------------------------------------------
extern "C" void kernel_launch(void* const* d_in, const int* in_sizes, int n_in,
                              void* d_out, int out_size)
{
    const float* query = (const float*)d_in[0];
    const float* key   = (const float*)d_in[1];
    const float* value = (const float*)d_in[2];
    const float* wq    = (const float*)d_in[3];
    const float* wk    = (const float*)d_in[4];
    const float* wv    = (const float*)d_in[5];
    const float* wp    = (const float*)d_in[6];
    const float* bias  = (const float*)d_in[7];
    float* out = (float*)d_out;

    cudaFuncSetAttribute(qkv_mma,   cudaFuncAttributeMaxDynamicSharedMemorySize, Q_SMEM);
    cudaFuncSetAttribute(flash_mma, cudaFuncAttributeMaxDynamicSharedMemorySize, FL_SMEM);
    cudaFuncSetAttribute(out_mma,   cudaFuncAttributeMaxDynamicSharedMemorySize, O_SMEM);

    qkv_mma<<<dim3(T_/128, (H_*HS_)/128, 3*B_), 256, Q_SMEM>>>(query, key, value, wq, wk, wv);
    flash_mma<<<dim3(T_/128, H_, B_), 256, FL_SMEM>>>();
    out_mma<<<dim3((B_*T_)/128, D_/64), 256, O_SMEM>>>(wp, bias, out);
}

// round 11
// speedup vs baseline: 4.3480x; 1.2371x over previous
#include <cuda_runtime.h>
#include <cuda_bf16.h>
#include <cstdint>

// Problem constants
constexpr int B_  = 2;
constexpr int T_  = 2048;
constexpr int S_  = 2048;
constexpr int D_  = 512;
constexpr int H_  = 8;
constexpr int HS_ = 64;

// Scratch (device globals). All mma operands stored PRE-ROUNDED to tf32 bits.
__device__ float g_Q  [B_*H_*T_*HS_];   // [B,H,T,HS] scaled by 0.125*log2e
__device__ float g_K  [B_*H_*S_*HS_];   // [B,H,S,HS]
__device__ float g_Vt [B_*H_*HS_*S_];   // [B,H,HS,S]  (transposed V)
__device__ float g_MH [B_*T_*H_*HS_];   // [B,T,H,HS]
__device__ float g_XR [3][B_*T_*D_];    // rounded q/k/v inputs
__device__ float g_WT [3][D_*D_];       // rounded qkv weights, [n=h*64+hs][k]
__device__ float g_WPT[D_*D_];          // rounded proj weight, [n][k]

// ---------------------------------------------------------------------------
// helpers
// ---------------------------------------------------------------------------
__device__ __forceinline__ float to_tf32(float x) {
    asm("cvt.rna.tf32.f32 %0, %0;" : "+f"(x));
    return x;
}
__device__ __forceinline__ unsigned f2u(float x) { return __float_as_uint(x); }

__device__ __forceinline__ void mma_tf32(float d[4], const unsigned a[4], const unsigned b[2]) {
    asm volatile(
        "mma.sync.aligned.m16n8k8.row.col.f32.tf32.tf32.f32 "
        "{%0,%1,%2,%3}, {%4,%5,%6,%7}, {%8,%9}, {%0,%1,%2,%3};"
        : "+f"(d[0]), "+f"(d[1]), "+f"(d[2]), "+f"(d[3])
        : "r"(a[0]), "r"(a[1]), "r"(a[2]), "r"(a[3]),
          "r"(b[0]), "r"(b[1]));
}

// ldmatrix x4: 4 fragment regs per instruction (tf32 elements as b16 pairs)
__device__ __forceinline__ void ldsm4(unsigned r[4], uint32_t addr) {
    asm volatile("ldmatrix.sync.aligned.m8n8.x4.shared.b16 {%0,%1,%2,%3}, [%4];"
        : "=r"(r[0]), "=r"(r[1]), "=r"(r[2]), "=r"(r[3]) : "r"(addr));
}

__device__ __forceinline__ float ex2(float x) {
    float y; asm("ex2.approx.ftz.f32 %0, %1;" : "=f"(y) : "f"(x)); return y;
}

__device__ __forceinline__ void cp16(uint32_t dst, const void* src) {
    asm volatile("cp.async.ca.shared.global [%0], [%1], 16;" :: "r"(dst), "l"(src));
}
#define CP_COMMIT()  asm volatile("cp.async.commit_group;")
#define CP_WAIT(n)   asm volatile("cp.async.wait_group %0;" :: "n"(n))

__device__ __forceinline__ uint32_t smem_u32_of(const void* p) {
    return (uint32_t)__cvta_generic_to_shared(p);
}

constexpr float QSCALE = 0.125f * 1.4426950408889634f;   // 1/sqrt(HS) * log2(e)

// ---------------------------------------------------------------------------
// Pre-pass 1: round q/k/v inputs to tf32 (mma A operands read raw via LDSM)
// ---------------------------------------------------------------------------
__global__ __launch_bounds__(256) void prep_inputs(
    const float* __restrict__ q, const float* __restrict__ k, const float* __restrict__ v)
{
    int i = blockIdx.x * 256 + threadIdx.x;
    if (i >= B_*T_*D_/4) return;
    float4 a = ((const float4*)q)[i], b = ((const float4*)k)[i], c = ((const float4*)v)[i];
    a.x=to_tf32(a.x); a.y=to_tf32(a.y); a.z=to_tf32(a.z); a.w=to_tf32(a.w);
    b.x=to_tf32(b.x); b.y=to_tf32(b.y); b.z=to_tf32(b.z); b.w=to_tf32(b.w);
    c.x=to_tf32(c.x); c.y=to_tf32(c.y); c.z=to_tf32(c.z); c.w=to_tf32(c.w);
    ((float4*)g_XR[0])[i] = a;
    ((float4*)g_XR[1])[i] = b;
    ((float4*)g_XR[2])[i] = c;
}

// ---------------------------------------------------------------------------
// Pre-pass 2: tiled transpose + round of weights into [n][k] form.
// grid (8, 8, 4): 64x64 tiles; z = which (0/1/2 = wq/wk/wv, 3 = wp)
// ---------------------------------------------------------------------------
__global__ __launch_bounds__(256) void prep_weights(
    const float* __restrict__ wq, const float* __restrict__ wk,
    const float* __restrict__ wv, const float* __restrict__ wp)
{
    __shared__ float t[64][65];
    const int which = blockIdx.z;
    const int k0 = blockIdx.x * 64, n0 = blockIdx.y * 64;
    const int tid = threadIdx.x;
    const float* srcw = (which == 0) ? wq : (which == 1) ? wk : (which == 2) ? wv : wp;

    #pragma unroll
    for (int i = 0; i < 16; i++) {
        int e = tid + i * 256;          // 4096 elements
        int r = e >> 6, c = e & 63;     // r = k-local, c = n-local
        float v;
        if (which == 3) v = srcw[(size_t)(k0 + r) * D_ + n0 + c];
        else            v = srcw[((size_t)(n0 >> 6) * D_ + k0 + r) * HS_ + c];
        t[r][c] = to_tf32(v);
    }
    __syncthreads();
    float* dst = (which == 3) ? g_WPT : g_WT[which];
    #pragma unroll
    for (int i = 0; i < 16; i++) {
        int e = tid + i * 256;
        int nl = e >> 6, kl = e & 63;
        dst[(size_t)(n0 + nl) * D_ + k0 + kl] = t[kl][nl];
    }
}

// ---------------------------------------------------------------------------
// Shared tf32 GEMM body: D[128,128] = A[128,512] @ Bm[128,512]^T
// cp.async 2-stage, LDSM fragments, legacy mma. block=256 (8 warps = 4m x 2n)
// ---------------------------------------------------------------------------
constexpr int GST   = 36;                      // smem row stride (floats)
constexpr int GTB   = 128 * GST * 4;           // operand stage bytes (18432)
constexpr int G_SMEM = 2 * 2 * GTB;            // 73728

template <class Epi>
__device__ __forceinline__ void gemm_body(
    const float* __restrict__ A, const float* __restrict__ Bm,
    int row0, int n0, Epi epi)
{
    extern __shared__ __align__(16) float gsm[];
    const uint32_t sb = smem_u32_of(gsm);
    const int tid = threadIdx.x, lane = tid & 31, w = tid >> 5;
    const int wm = w & 3, wn = w >> 2;
    const int p = lane >> 2, q = lane & 3;
    const int ls = lane & 7, seg = lane >> 3;

    int cr[4], cc[4];
    #pragma unroll
    for (int i = 0; i < 4; i++) {
        int idx = tid + i * 256;
        cr[i] = idx >> 3; cc[i] = (idx & 7) * 4;
    }

    auto issue = [&](int kc) {
        uint32_t ab = sb + (uint32_t)(kc & 1) * (2 * GTB);
        uint32_t bb = ab + GTB;
        int k0 = kc * 32;
        #pragma unroll
        for (int i = 0; i < 4; i++) {
            uint32_t off = (uint32_t)((cr[i] * GST + cc[i]) * 4);
            cp16(ab + off, A  + (size_t)(row0 + cr[i]) * D_ + k0 + cc[i]);
            cp16(bb + off, Bm + (size_t)(n0   + cr[i]) * D_ + k0 + cc[i]);
        }
        CP_COMMIT();
    };

    issue(0);
    float C[2][8][4] = {};

    for (int kc = 0; kc < 16; kc++) {
        if (kc + 1 < 16) { issue(kc + 1); CP_WAIT(1); }
        else             { CP_WAIT(0); }
        __syncthreads();

        uint32_t ab = sb + (uint32_t)(kc & 1) * (2 * GTB);
        uint32_t bb = ab + GTB;
        // A-frag base: rows wm*32 + (seg&1)*8 + ls, col (seg>>1)*4
        uint32_t aaddr = ab + (uint32_t)(((wm*32 + (seg&1)*8 + ls) * GST + (seg>>1)*4) * 4);
        // B-frag base: rows wn*64 + (seg>>1)*8 + ls, col (seg&1)*4
        uint32_t baddr = bb + (uint32_t)(((wn*64 + (seg>>1)*8 + ls) * GST + (seg&1)*4) * 4);

        #pragma unroll
        for (int ks = 0; ks < 4; ks++) {
            unsigned af[2][4];
            ldsm4(af[0], aaddr + (uint32_t)(ks * 32));
            ldsm4(af[1], aaddr + (uint32_t)(16 * GST * 4 + ks * 32));
            #pragma unroll
            for (int ntp = 0; ntp < 4; ntp++) {
                unsigned bq[4];
                ldsm4(bq, baddr + (uint32_t)(ntp * 16 * GST * 4 + ks * 32));
                unsigned b0[2] = { bq[0], bq[1] };
                unsigned b1[2] = { bq[2], bq[3] };
                mma_tf32(C[0][2*ntp  ], af[0], b0);
                mma_tf32(C[0][2*ntp+1], af[0], b1);
                mma_tf32(C[1][2*ntp  ], af[1], b0);
                mma_tf32(C[1][2*ntp+1], af[1], b1);
            }
        }
        __syncthreads();
    }

    #pragma unroll
    for (int mt = 0; mt < 2; mt++) {
        int r = row0 + wm*32 + mt*16 + p;
        #pragma unroll
        for (int nt = 0; nt < 8; nt++) {
            int c = n0 + wn*64 + nt*8 + 2*q;
            epi(r, c, C[mt][nt][0], C[mt][nt][1], C[mt][nt][2], C[mt][nt][3]);
        }
    }
}

// ---------------------------------------------------------------------------
// Kernel 1: QKV projection. grid (T/128, 4, 3B), block 256.
// ---------------------------------------------------------------------------
__global__ __launch_bounds__(256, 2) void qkv_g()
{
    const int which = blockIdx.z % 3;
    const int b     = blockIdx.z / 3;
    const int n0    = blockIdx.y * 128;
    const int row0  = blockIdx.x * 128;

    const float* A  = g_XR[which] + (size_t)b * T_ * D_;
    const float* Bm = g_WT[which];

    if (which == 0) {
        gemm_body(A, Bm, row0, n0, [&](int r, int c, float v0, float v1, float v2, float v3) {
            int head = c >> 6, hs = c & 63;
            float* o0 = g_Q + ((size_t)(b*H_ + head) * T_ + r    ) * HS_ + hs;
            float* o1 = g_Q + ((size_t)(b*H_ + head) * T_ + r + 8) * HS_ + hs;
            *(float2*)o0 = make_float2(to_tf32(v0*QSCALE), to_tf32(v1*QSCALE));
            *(float2*)o1 = make_float2(to_tf32(v2*QSCALE), to_tf32(v3*QSCALE));
        });
    } else if (which == 1) {
        gemm_body(A, Bm, row0, n0, [&](int r, int c, float v0, float v1, float v2, float v3) {
            int head = c >> 6, hs = c & 63;
            float* o0 = g_K + ((size_t)(b*H_ + head) * T_ + r    ) * HS_ + hs;
            float* o1 = g_K + ((size_t)(b*H_ + head) * T_ + r + 8) * HS_ + hs;
            *(float2*)o0 = make_float2(to_tf32(v0), to_tf32(v1));
            *(float2*)o1 = make_float2(to_tf32(v2), to_tf32(v3));
        });
    } else {
        gemm_body(A, Bm, row0, n0, [&](int r, int c, float v0, float v1, float v2, float v3) {
            int head = c >> 6, hs = c & 63;
            float* base = g_Vt + ((size_t)(b*H_ + head) * HS_ + hs) * S_;
            base[r]          = to_tf32(v0);      // (hs,   token r)
            base[S_ + r]     = to_tf32(v1);      // (hs+1, token r)
            base[r + 8]      = to_tf32(v2);
            base[S_ + r + 8] = to_tf32(v3);
        });
    }
}

// ---------------------------------------------------------------------------
// Kernel 3: output projection. grid (32, 4), block 256.
// ---------------------------------------------------------------------------
__global__ __launch_bounds__(256, 2) void out_g(const float* __restrict__ bias,
                                                float* __restrict__ out)
{
    const int n0   = blockIdx.y * 128;
    const int row0 = blockIdx.x * 128;
    gemm_body(g_MH, g_WPT, row0, n0, [&](int r, int c, float v0, float v1, float v2, float v3) {
        float2 bb = *(const float2*)&bias[c];
        *(float2*)&out[(size_t)r     * D_ + c] = make_float2(v0 + bb.x, v1 + bb.y);
        *(float2*)&out[(size_t)(r+8) * D_ + c] = make_float2(v2 + bb.x, v3 + bb.y);
    });
}

// ---------------------------------------------------------------------------
// Kernel 2: flash attention. grid (T/128, H, B), block 256 (8 warps x 16 rows).
// SMEM: Qs[128][68] (-> P buffer), double-buffered K[64][68] + Vt[64][68].
// LDSM for K, V (transposed layout) and P fragments.
// ---------------------------------------------------------------------------
constexpr int FLS     = 68;
constexpr int NT      = S_ / 64;
constexpr int FL_SMEM = (128 + 4*64) * FLS * (int)sizeof(float);   // 104448 B

__global__ __launch_bounds__(256, 2) void flash_g()
{
    extern __shared__ __align__(16) float sm[];
    float* Qs = sm;
    const uint32_t smem_u32 = smem_u32_of(sm);

    const int b    = blockIdx.z;
    const int h    = blockIdx.y;
    const int q0   = blockIdx.x * 128;
    const int tid  = threadIdx.x;
    const int w    = tid >> 5;
    const int lane = tid & 31;
    const int p    = lane >> 2;
    const int q    = lane & 3;
    const int ls   = lane & 7;
    const int seg  = lane >> 3;
    const int r0   = w * 16 + p;

    const float* Qg  = g_Q  + ((size_t)(b * H_ + h) * T_ + q0) * HS_;
    const float* Kg  = g_K  + (size_t)(b * H_ + h) * S_ * HS_;
    const float* Vtg = g_Vt + (size_t)(b * H_ + h) * HS_ * S_;

    // prologue: Q tile
    #pragma unroll
    for (int i = 0; i < 8; i++) {
        int idx = tid + i * 256;
        int r = idx >> 4, c = (idx & 15) * 4;
        cp16(smem_u32 + (uint32_t)((r*FLS + c)*4), Qg + (size_t)r*HS_ + c);
    }
    CP_COMMIT();

    auto issue_tile = [&](int t, int s) {
        const float* Kp = Kg + (size_t)t * 64 * HS_;
        const uint32_t kb = smem_u32 + (uint32_t)((128 + s*128) * FLS * 4);
        const uint32_t vb = kb + (uint32_t)(64 * FLS * 4);
        #pragma unroll
        for (int i = 0; i < 4; i++) {
            int idx = tid + i * 256;
            int r = idx >> 4, c = (idx & 15) * 4;
            uint32_t doff = (uint32_t)((r*FLS + c)*4);
            cp16(kb + doff, Kp + (size_t)r*HS_ + c);                  // K[s][d]
            cp16(vb + doff, Vtg + (size_t)r*S_ + (size_t)t*64 + c);   // Vt[hs][s]
        }
        CP_COMMIT();
    };

    issue_tile(0, 0);
    CP_WAIT(1);
    __syncthreads();

    // A-frag base for Q / P (warp-private rows w*16..w*16+15)
    const uint32_t qaddr = smem_u32 +
        (uint32_t)(((w*16 + (seg&1)*8 + ls) * FLS + (seg>>1)*4) * 4);
    // K B-frag lane offset: rows nt*8+ls, col ktp*16 + (seg>>1)*8 + (seg&1)*4
    const uint32_t kfrag = (uint32_t)((ls * FLS + (seg>>1)*8 + (seg&1)*4) * 4);
    // V B-frag lane offset: rows ntp*16 + (seg>>1)*8 + ls, col kt*8 + (seg&1)*4
    const uint32_t vfrag = (uint32_t)((((seg>>1)*8 + ls) * FLS + (seg&1)*4) * 4);

    unsigned qf[8][4];
    #pragma unroll
    for (int kt = 0; kt < 8; kt++) ldsm4(qf[kt], qaddr + (uint32_t)(kt * 32));

    float O[8][4] = {};
    float m0 = -1e30f, m1 = -1e30f, l0 = 0.f, l1 = 0.f;

    for (int t = 0; t < NT; t++) {
        if (t + 1 < NT) { issue_tile(t + 1, (t + 1) & 1); CP_WAIT(1); }
        else            { CP_WAIT(0); }
        __syncthreads();

        const uint32_t kb = smem_u32 + (uint32_t)((128 + (t & 1)*128) * FLS * 4);
        const uint32_t vb = kb + (uint32_t)(64 * FLS * 4);

        // S = Q @ K^T
        float Sf[8][4] = {};
        #pragma unroll
        for (int nt = 0; nt < 8; nt++) {
            uint32_t krow = kb + kfrag + (uint32_t)(nt * 8 * FLS * 4);
            #pragma unroll
            for (int ktp = 0; ktp < 4; ktp++) {
                unsigned bq[4];
                ldsm4(bq, krow + (uint32_t)(ktp * 64));
                unsigned c0[2] = { bq[0], bq[1] };
                unsigned c1[2] = { bq[2], bq[3] };
                mma_tf32(Sf[nt], qf[2*ktp  ], c0);
                mma_tf32(Sf[nt], qf[2*ktp+1], c1);
            }
        }

        // online softmax (base-2; Q pre-scaled by log2e/8)
        float tm0 = -1e30f, tm1 = -1e30f;
        #pragma unroll
        for (int nt = 0; nt < 8; nt++) {
            tm0 = fmaxf(tm0, fmaxf(Sf[nt][0], Sf[nt][1]));
            tm1 = fmaxf(tm1, fmaxf(Sf[nt][2], Sf[nt][3]));
        }
        tm0 = fmaxf(tm0, __shfl_xor_sync(0xffffffffu, tm0, 1));
        tm0 = fmaxf(tm0, __shfl_xor_sync(0xffffffffu, tm0, 2));
        tm1 = fmaxf(tm1, __shfl_xor_sync(0xffffffffu, tm1, 1));
        tm1 = fmaxf(tm1, __shfl_xor_sync(0xffffffffu, tm1, 2));
        float mn0 = fmaxf(m0, tm0), mn1 = fmaxf(m1, tm1);
        float a0  = ex2(m0 - mn0), a1 = ex2(m1 - mn1);

        float ts0 = 0.f, ts1 = 0.f;
        #pragma unroll
        for (int nt = 0; nt < 8; nt++) {
            float p00 = ex2(Sf[nt][0] - mn0);
            float p01 = ex2(Sf[nt][1] - mn0);
            float p10 = ex2(Sf[nt][2] - mn1);
            float p11 = ex2(Sf[nt][3] - mn1);
            ts0 += p00 + p01;
            ts1 += p10 + p11;
            *(float2*)&Qs[ r0   *FLS + nt*8 + 2*q] = make_float2(to_tf32(p00), to_tf32(p01));
            *(float2*)&Qs[(r0+8)*FLS + nt*8 + 2*q] = make_float2(to_tf32(p10), to_tf32(p11));
        }
        ts0 += __shfl_xor_sync(0xffffffffu, ts0, 1);
        ts0 += __shfl_xor_sync(0xffffffffu, ts0, 2);
        ts1 += __shfl_xor_sync(0xffffffffu, ts1, 1);
        ts1 += __shfl_xor_sync(0xffffffffu, ts1, 2);
        l0 = l0 * a0 + ts0;
        l1 = l1 * a1 + ts1;
        m0 = mn0; m1 = mn1;

        #pragma unroll
        for (int nt = 0; nt < 8; nt++) {
            O[nt][0] *= a0; O[nt][1] *= a0;
            O[nt][2] *= a1; O[nt][3] *= a1;
        }
        __syncwarp();   // order P stores (warp-private rows) before LDSM reads

        // O += P @ V  (V transposed in SMEM: rows = hs, cols = s)
        #pragma unroll
        for (int kt = 0; kt < 8; kt++) {
            unsigned af[4];
            ldsm4(af, qaddr + (uint32_t)(kt * 32));
            #pragma unroll
            for (int ntp = 0; ntp < 4; ntp++) {
                unsigned bv[4];
                ldsm4(bv, vb + vfrag + (uint32_t)((ntp*16*FLS + kt*8) * 4));
                unsigned c0[2] = { bv[0], bv[1] };
                unsigned c1[2] = { bv[2], bv[3] };
                mma_tf32(O[2*ntp  ], af, c0);
                mma_tf32(O[2*ntp+1], af, c1);
            }
        }
        __syncthreads();
    }

    // epilogue: normalize, round (A operand of out-proj), store [B,T,H,HS]
    float inv0 = 1.0f / l0, inv1 = 1.0f / l1;
    int tq = q0 + r0;
    float* o0 = g_MH + ((size_t)(b * T_ + tq    ) * H_ + h) * HS_;
    float* o1 = g_MH + ((size_t)(b * T_ + tq + 8) * H_ + h) * HS_;
    #pragma unroll
    for (int nt = 0; nt < 8; nt++) {
        *(float2*)&o0[nt*8 + 2*q] = make_float2(to_tf32(O[nt][0]*inv0), to_tf32(O[nt][1]*inv0));
        *(float2*)&o1[nt*8 + 2*q] = make_float2(to_tf32(O[nt][2]*inv1), to_tf32(O[nt][3]*inv1));
    }
}

// ---------------------------------------------------------------------------
extern "C" void kernel_launch(void* const* d_in, const int* in_sizes, int n_in,
                              void* d_out, int out_size)
{
    const float* query = (const float*)d_in[0];
    const float* key   = (const float*)d_in[1];
    const float* value = (const float*)d_in[2];
    const float* wq    = (const float*)d_in[3];
    const float* wk    = (const float*)d_in[4];
    const float* wv    = (const float*)d_in[5];
    const float* wp    = (const float*)d_in[6];
    const float* bias  = (const float*)d_in[7];
    float* out = (float*)d_out;

    cudaFuncSetAttribute(qkv_g,   cudaFuncAttributeMaxDynamicSharedMemorySize, G_SMEM);
    cudaFuncSetAttribute(out_g,   cudaFuncAttributeMaxDynamicSharedMemorySize, G_SMEM);
    cudaFuncSetAttribute(flash_g, cudaFuncAttributeMaxDynamicSharedMemorySize, FL_SMEM);

    prep_inputs <<<(B_*T_*D_/4 + 255)/256, 256>>>(query, key, value);
    prep_weights<<<dim3(8, 8, 4), 256>>>(wq, wk, wv, wp);
    qkv_g <<<dim3(T_/128, D_/128, 3*B_), 256, G_SMEM>>>();
    flash_g<<<dim3(T_/128, H_, B_), 256, FL_SMEM>>>();
    out_g <<<dim3((B_*T_)/128, D_/128), 256, G_SMEM>>>(bias, out);
}

// round 12
// speedup vs baseline: 4.5769x; 1.0526x over previous
#include <cuda_runtime.h>
#include <cuda_bf16.h>
#include <cstdint>

// Problem constants
constexpr int B_  = 2;
constexpr int T_  = 2048;
constexpr int S_  = 2048;
constexpr int D_  = 512;
constexpr int H_  = 8;
constexpr int HS_ = 64;

// Scratch (device globals). All mma operands stored PRE-ROUNDED to tf32 bits.
__device__ float g_Q  [B_*H_*T_*HS_];   // [B,H,T,HS] scaled by 0.125*log2e
__device__ float g_K  [B_*H_*S_*HS_];   // [B,H,S,HS]
__device__ float g_Vt [B_*H_*HS_*S_];   // [B,H,HS,S]  (transposed V)
__device__ float g_MH [B_*T_*H_*HS_];   // [B,T,H,HS]
__device__ float g_XR [3][B_*T_*D_];    // rounded q/k/v inputs
__device__ float g_WT [3][D_*D_];       // rounded qkv weights, [n=h*64+hs][k]
__device__ float g_WPT[D_*D_];          // rounded proj weight, [n][k]

// ---------------------------------------------------------------------------
// helpers
// ---------------------------------------------------------------------------
__device__ __forceinline__ float to_tf32(float x) {
    asm("cvt.rna.tf32.f32 %0, %0;" : "+f"(x));
    return x;
}
__device__ __forceinline__ unsigned f2u(float x) { return __float_as_uint(x); }

__device__ __forceinline__ void mma_tf32(float d[4], const unsigned a[4], const unsigned b[2]) {
    asm volatile(
        "mma.sync.aligned.m16n8k8.row.col.f32.tf32.tf32.f32 "
        "{%0,%1,%2,%3}, {%4,%5,%6,%7}, {%8,%9}, {%0,%1,%2,%3};"
        : "+f"(d[0]), "+f"(d[1]), "+f"(d[2]), "+f"(d[3])
        : "r"(a[0]), "r"(a[1]), "r"(a[2]), "r"(a[3]),
          "r"(b[0]), "r"(b[1]));
}

// ldmatrix x4: 4 fragment regs per instruction (tf32 elements as b16 pairs)
__device__ __forceinline__ void ldsm4(unsigned r[4], uint32_t addr) {
    asm volatile("ldmatrix.sync.aligned.m8n8.x4.shared.b16 {%0,%1,%2,%3}, [%4];"
        : "=r"(r[0]), "=r"(r[1]), "=r"(r[2]), "=r"(r[3]) : "r"(addr));
}

__device__ __forceinline__ float ex2(float x) {
    float y; asm("ex2.approx.ftz.f32 %0, %1;" : "=f"(y) : "f"(x)); return y;
}

__device__ __forceinline__ void cp16(uint32_t dst, const void* src) {
    asm volatile("cp.async.ca.shared.global [%0], [%1], 16;" :: "r"(dst), "l"(src));
}
#define CP_COMMIT()  asm volatile("cp.async.commit_group;")
#define CP_WAIT(n)   asm volatile("cp.async.wait_group %0;" :: "n"(n))

__device__ __forceinline__ uint32_t smem_u32_of(const void* p) {
    return (uint32_t)__cvta_generic_to_shared(p);
}

constexpr float QSCALE = 0.125f * 1.4426950408889634f;   // 1/sqrt(HS) * log2(e)

// ---------------------------------------------------------------------------
// Pre-pass 1: round q/k/v inputs to tf32
// ---------------------------------------------------------------------------
__global__ __launch_bounds__(256) void prep_inputs(
    const float* __restrict__ q, const float* __restrict__ k, const float* __restrict__ v)
{
    int i = blockIdx.x * 256 + threadIdx.x;
    if (i >= B_*T_*D_/4) return;
    float4 a = ((const float4*)q)[i], b = ((const float4*)k)[i], c = ((const float4*)v)[i];
    a.x=to_tf32(a.x); a.y=to_tf32(a.y); a.z=to_tf32(a.z); a.w=to_tf32(a.w);
    b.x=to_tf32(b.x); b.y=to_tf32(b.y); b.z=to_tf32(b.z); b.w=to_tf32(b.w);
    c.x=to_tf32(c.x); c.y=to_tf32(c.y); c.z=to_tf32(c.z); c.w=to_tf32(c.w);
    ((float4*)g_XR[0])[i] = a;
    ((float4*)g_XR[1])[i] = b;
    ((float4*)g_XR[2])[i] = c;
}

// ---------------------------------------------------------------------------
// Pre-pass 2: tiled transpose + round of weights into [n][k] form.
// grid (8, 8, 4): 64x64 tiles; z = which (0/1/2 = wq/wk/wv, 3 = wp)
// ---------------------------------------------------------------------------
__global__ __launch_bounds__(256) void prep_weights(
    const float* __restrict__ wq, const float* __restrict__ wk,
    const float* __restrict__ wv, const float* __restrict__ wp)
{
    __shared__ float t[64][65];
    const int which = blockIdx.z;
    const int k0 = blockIdx.x * 64, n0 = blockIdx.y * 64;
    const int tid = threadIdx.x;
    const float* srcw = (which == 0) ? wq : (which == 1) ? wk : (which == 2) ? wv : wp;

    #pragma unroll
    for (int i = 0; i < 16; i++) {
        int e = tid + i * 256;          // 4096 elements
        int r = e >> 6, c = e & 63;     // r = k-local, c = n-local
        float v;
        if (which == 3) v = srcw[(size_t)(k0 + r) * D_ + n0 + c];
        else            v = srcw[((size_t)(n0 >> 6) * D_ + k0 + r) * HS_ + c];
        t[r][c] = to_tf32(v);
    }
    __syncthreads();
    float* dst = (which == 3) ? g_WPT : g_WT[which];
    #pragma unroll
    for (int i = 0; i < 16; i++) {
        int e = tid + i * 256;
        int nl = e >> 6, kl = e & 63;
        dst[(size_t)(n0 + nl) * D_ + k0 + kl] = t[kl][nl];
    }
}

// ---------------------------------------------------------------------------
// Shared tf32 GEMM body: D[128,128] = A[128,512] @ Bm[128,512]^T
// cp.async 2-stage, LDSM fragments, legacy mma. block=256 (8 warps = 4m x 2n)
// ---------------------------------------------------------------------------
constexpr int GST   = 36;                      // smem row stride (floats)
constexpr int GTB   = 128 * GST * 4;           // operand stage bytes (18432)
constexpr int G_SMEM = 2 * 2 * GTB;            // 73728

template <class Epi>
__device__ __forceinline__ void gemm_body(
    const float* __restrict__ A, const float* __restrict__ Bm,
    int row0, int n0, Epi epi)
{
    extern __shared__ __align__(16) float gsm[];
    const uint32_t sb = smem_u32_of(gsm);
    const int tid = threadIdx.x, lane = tid & 31, w = tid >> 5;
    const int wm = w & 3, wn = w >> 2;
    const int p = lane >> 2, q = lane & 3;
    const int ls = lane & 7, seg = lane >> 3;

    int cr[4], cc[4];
    #pragma unroll
    for (int i = 0; i < 4; i++) {
        int idx = tid + i * 256;
        cr[i] = idx >> 3; cc[i] = (idx & 7) * 4;
    }

    auto issue = [&](int kc) {
        uint32_t ab = sb + (uint32_t)(kc & 1) * (2 * GTB);
        uint32_t bb = ab + GTB;
        int k0 = kc * 32;
        #pragma unroll
        for (int i = 0; i < 4; i++) {
            uint32_t off = (uint32_t)((cr[i] * GST + cc[i]) * 4);
            cp16(ab + off, A  + (size_t)(row0 + cr[i]) * D_ + k0 + cc[i]);
            cp16(bb + off, Bm + (size_t)(n0   + cr[i]) * D_ + k0 + cc[i]);
        }
        CP_COMMIT();
    };

    issue(0);
    float C[2][8][4] = {};

    for (int kc = 0; kc < 16; kc++) {
        if (kc + 1 < 16) { issue(kc + 1); CP_WAIT(1); }
        else             { CP_WAIT(0); }
        __syncthreads();

        uint32_t ab = sb + (uint32_t)(kc & 1) * (2 * GTB);
        uint32_t bb = ab + GTB;
        uint32_t aaddr = ab + (uint32_t)(((wm*32 + (seg&1)*8 + ls) * GST + (seg>>1)*4) * 4);
        uint32_t baddr = bb + (uint32_t)(((wn*64 + (seg>>1)*8 + ls) * GST + (seg&1)*4) * 4);

        #pragma unroll
        for (int ks = 0; ks < 4; ks++) {
            unsigned af[2][4];
            ldsm4(af[0], aaddr + (uint32_t)(ks * 32));
            ldsm4(af[1], aaddr + (uint32_t)(16 * GST * 4 + ks * 32));
            #pragma unroll
            for (int ntp = 0; ntp < 4; ntp++) {
                unsigned bq[4];
                ldsm4(bq, baddr + (uint32_t)(ntp * 16 * GST * 4 + ks * 32));
                unsigned b0[2] = { bq[0], bq[1] };
                unsigned b1[2] = { bq[2], bq[3] };
                mma_tf32(C[0][2*ntp  ], af[0], b0);
                mma_tf32(C[0][2*ntp+1], af[0], b1);
                mma_tf32(C[1][2*ntp  ], af[1], b0);
                mma_tf32(C[1][2*ntp+1], af[1], b1);
            }
        }
        __syncthreads();
    }

    #pragma unroll
    for (int mt = 0; mt < 2; mt++) {
        int r = row0 + wm*32 + mt*16 + p;
        #pragma unroll
        for (int nt = 0; nt < 8; nt++) {
            int c = n0 + wn*64 + nt*8 + 2*q;
            epi(r, c, C[mt][nt][0], C[mt][nt][1], C[mt][nt][2], C[mt][nt][3]);
        }
    }
}

// ---------------------------------------------------------------------------
// Kernel 1: QKV projection. grid (T/128, 4, 3B), block 256.
// ---------------------------------------------------------------------------
__global__ __launch_bounds__(256, 2) void qkv_g()
{
    const int which = blockIdx.z % 3;
    const int b     = blockIdx.z / 3;
    const int n0    = blockIdx.y * 128;
    const int row0  = blockIdx.x * 128;

    const float* A  = g_XR[which] + (size_t)b * T_ * D_;
    const float* Bm = g_WT[which];

    if (which == 0) {
        gemm_body(A, Bm, row0, n0, [&](int r, int c, float v0, float v1, float v2, float v3) {
            int head = c >> 6, hs = c & 63;
            float* o0 = g_Q + ((size_t)(b*H_ + head) * T_ + r    ) * HS_ + hs;
            float* o1 = g_Q + ((size_t)(b*H_ + head) * T_ + r + 8) * HS_ + hs;
            *(float2*)o0 = make_float2(to_tf32(v0*QSCALE), to_tf32(v1*QSCALE));
            *(float2*)o1 = make_float2(to_tf32(v2*QSCALE), to_tf32(v3*QSCALE));
        });
    } else if (which == 1) {
        gemm_body(A, Bm, row0, n0, [&](int r, int c, float v0, float v1, float v2, float v3) {
            int head = c >> 6, hs = c & 63;
            float* o0 = g_K + ((size_t)(b*H_ + head) * T_ + r    ) * HS_ + hs;
            float* o1 = g_K + ((size_t)(b*H_ + head) * T_ + r + 8) * HS_ + hs;
            *(float2*)o0 = make_float2(to_tf32(v0), to_tf32(v1));
            *(float2*)o1 = make_float2(to_tf32(v2), to_tf32(v3));
        });
    } else {
        gemm_body(A, Bm, row0, n0, [&](int r, int c, float v0, float v1, float v2, float v3) {
            int head = c >> 6, hs = c & 63;
            float* base = g_Vt + ((size_t)(b*H_ + head) * HS_ + hs) * S_;
            base[r]          = to_tf32(v0);
            base[S_ + r]     = to_tf32(v1);
            base[r + 8]      = to_tf32(v2);
            base[S_ + r + 8] = to_tf32(v3);
        });
    }
}

// ---------------------------------------------------------------------------
// Kernel 3: output projection. grid (32, 4), block 256.
// ---------------------------------------------------------------------------
__global__ __launch_bounds__(256, 2) void out_g(const float* __restrict__ bias,
                                                float* __restrict__ out)
{
    const int n0   = blockIdx.y * 128;
    const int row0 = blockIdx.x * 128;
    gemm_body(g_MH, g_WPT, row0, n0, [&](int r, int c, float v0, float v1, float v2, float v3) {
        float2 bb = *(const float2*)&bias[c];
        *(float2*)&out[(size_t)r     * D_ + c] = make_float2(v0 + bb.x, v1 + bb.y);
        *(float2*)&out[(size_t)(r+8) * D_ + c] = make_float2(v2 + bb.x, v3 + bb.y);
    });
}

// ---------------------------------------------------------------------------
// Kernel 2: flash attention. grid (T/128, H, B), block 128 (4 warps x 32 rows).
// SMEM: Qs[128][68] (-> P buffer), double-buffered K[64][68] + Vt[64][68].
// Each warp owns 32 query rows -> K/V fragments amortized over 2x rows.
// ---------------------------------------------------------------------------
constexpr int FLS     = 68;
constexpr int NT      = S_ / 64;
constexpr int FL_SMEM = (128 + 4*64) * FLS * (int)sizeof(float);   // 104448 B

__global__ __launch_bounds__(128, 2) void flash_g()
{
    extern __shared__ __align__(16) float sm[];
    float* Qs = sm;
    const uint32_t smem_u32 = smem_u32_of(sm);

    const int b    = blockIdx.z;
    const int h    = blockIdx.y;
    const int q0   = blockIdx.x * 128;
    const int tid  = threadIdx.x;
    const int w    = tid >> 5;           // 4 warps
    const int lane = tid & 31;
    const int p    = lane >> 2;
    const int q    = lane & 3;
    const int ls   = lane & 7;
    const int seg  = lane >> 3;
    const int r0   = w * 32 + p;         // warp owns rows [w*32, w*32+32)

    const float* Qg  = g_Q  + ((size_t)(b * H_ + h) * T_ + q0) * HS_;
    const float* Kg  = g_K  + (size_t)(b * H_ + h) * S_ * HS_;
    const float* Vtg = g_Vt + (size_t)(b * H_ + h) * HS_ * S_;

    // prologue: Q tile (128x64) = 2048 float4, 16 per thread
    #pragma unroll
    for (int i = 0; i < 16; i++) {
        int idx = tid + i * 128;
        int r = idx >> 4, c = (idx & 15) * 4;
        cp16(smem_u32 + (uint32_t)((r*FLS + c)*4), Qg + (size_t)r*HS_ + c);
    }
    CP_COMMIT();

    auto issue_tile = [&](int t, int s) {
        const float* Kp = Kg + (size_t)t * 64 * HS_;
        const uint32_t kb = smem_u32 + (uint32_t)((128 + s*128) * FLS * 4);
        const uint32_t vb = kb + (uint32_t)(64 * FLS * 4);
        #pragma unroll
        for (int i = 0; i < 8; i++) {
            int idx = tid + i * 128;
            int r = idx >> 4, c = (idx & 15) * 4;
            uint32_t doff = (uint32_t)((r*FLS + c)*4);
            cp16(kb + doff, Kp + (size_t)r*HS_ + c);                  // K[s][d]
            cp16(vb + doff, Vtg + (size_t)r*S_ + (size_t)t*64 + c);   // Vt[hs][s]
        }
        CP_COMMIT();
    };

    issue_tile(0, 0);
    CP_WAIT(1);
    __syncthreads();

    // fragment base addresses
    const uint32_t qaddr = smem_u32 +
        (uint32_t)(((w*32 + (seg&1)*8 + ls) * FLS + (seg>>1)*4) * 4);
    const uint32_t kfrag = (uint32_t)((ls * FLS + (seg>>1)*8 + (seg&1)*4) * 4);
    const uint32_t vfrag = (uint32_t)((((seg>>1)*8 + ls) * FLS + (seg&1)*4) * 4);

    // Q fragments: 2 m-tiles x 8 k-tiles (64 regs), reused over all KV tiles
    unsigned qf[2][8][4];
    #pragma unroll
    for (int mt = 0; mt < 2; mt++)
        #pragma unroll
        for (int kt = 0; kt < 8; kt++)
            ldsm4(qf[mt][kt], qaddr + (uint32_t)(mt * 16 * FLS * 4 + kt * 32));

    float O[2][8][4] = {};
    float m_[4] = {-1e30f, -1e30f, -1e30f, -1e30f};
    float l_[4] = {0.f, 0.f, 0.f, 0.f};

    for (int t = 0; t < NT; t++) {
        if (t + 1 < NT) { issue_tile(t + 1, (t + 1) & 1); CP_WAIT(1); }
        else            { CP_WAIT(0); }
        __syncthreads();

        const uint32_t kb = smem_u32 + (uint32_t)((128 + (t & 1)*128) * FLS * 4);
        const uint32_t vb = kb + (uint32_t)(64 * FLS * 4);

        // S = Q @ K^T : one K-fragment load feeds BOTH m-tiles
        float Sf[2][8][4] = {};
        #pragma unroll
        for (int nt = 0; nt < 8; nt++) {
            uint32_t krow = kb + kfrag + (uint32_t)(nt * 8 * FLS * 4);
            #pragma unroll
            for (int ktp = 0; ktp < 4; ktp++) {
                unsigned bq[4];
                ldsm4(bq, krow + (uint32_t)(ktp * 64));
                unsigned c0[2] = { bq[0], bq[1] };
                unsigned c1[2] = { bq[2], bq[3] };
                #pragma unroll
                for (int mt = 0; mt < 2; mt++) {
                    mma_tf32(Sf[mt][nt], qf[mt][2*ktp  ], c0);
                    mma_tf32(Sf[mt][nt], qf[mt][2*ktp+1], c1);
                }
            }
        }

        // online softmax; row groups: idx = 2*mt + half -> row r0 + mt*16 + half*8
        float tm[4] = {-1e30f, -1e30f, -1e30f, -1e30f};
        #pragma unroll
        for (int mt = 0; mt < 2; mt++)
            #pragma unroll
            for (int nt = 0; nt < 8; nt++) {
                tm[2*mt  ] = fmaxf(tm[2*mt  ], fmaxf(Sf[mt][nt][0], Sf[mt][nt][1]));
                tm[2*mt+1] = fmaxf(tm[2*mt+1], fmaxf(Sf[mt][nt][2], Sf[mt][nt][3]));
            }
        float mn[4], al[4], ts[4];
        #pragma unroll
        for (int i = 0; i < 4; i++) {
            tm[i] = fmaxf(tm[i], __shfl_xor_sync(0xffffffffu, tm[i], 1));
            tm[i] = fmaxf(tm[i], __shfl_xor_sync(0xffffffffu, tm[i], 2));
            mn[i] = fmaxf(m_[i], tm[i]);
            al[i] = ex2(m_[i] - mn[i]);
            ts[i] = 0.f;
        }

        #pragma unroll
        for (int mt = 0; mt < 2; mt++)
            #pragma unroll
            for (int nt = 0; nt < 8; nt++) {
                float p00 = ex2(Sf[mt][nt][0] - mn[2*mt  ]);
                float p01 = ex2(Sf[mt][nt][1] - mn[2*mt  ]);
                float p10 = ex2(Sf[mt][nt][2] - mn[2*mt+1]);
                float p11 = ex2(Sf[mt][nt][3] - mn[2*mt+1]);
                ts[2*mt  ] += p00 + p01;
                ts[2*mt+1] += p10 + p11;
                *(float2*)&Qs[(r0 + mt*16    )*FLS + nt*8 + 2*q] =
                    make_float2(to_tf32(p00), to_tf32(p01));
                *(float2*)&Qs[(r0 + mt*16 + 8)*FLS + nt*8 + 2*q] =
                    make_float2(to_tf32(p10), to_tf32(p11));
            }

        #pragma unroll
        for (int i = 0; i < 4; i++) {
            ts[i] += __shfl_xor_sync(0xffffffffu, ts[i], 1);
            ts[i] += __shfl_xor_sync(0xffffffffu, ts[i], 2);
            l_[i] = l_[i] * al[i] + ts[i];
            m_[i] = mn[i];
        }

        #pragma unroll
        for (int mt = 0; mt < 2; mt++)
            #pragma unroll
            for (int nt = 0; nt < 8; nt++) {
                O[mt][nt][0] *= al[2*mt  ]; O[mt][nt][1] *= al[2*mt  ];
                O[mt][nt][2] *= al[2*mt+1]; O[mt][nt][3] *= al[2*mt+1];
            }
        __syncwarp();   // order P stores (warp-private rows) before LDSM reads

        // O += P @ V : one V-fragment load feeds BOTH m-tiles
        #pragma unroll
        for (int kt = 0; kt < 8; kt++) {
            unsigned af[2][4];
            ldsm4(af[0], qaddr + (uint32_t)(kt * 32));
            ldsm4(af[1], qaddr + (uint32_t)(16 * FLS * 4 + kt * 32));
            #pragma unroll
            for (int ntp = 0; ntp < 4; ntp++) {
                unsigned bv[4];
                ldsm4(bv, vb + vfrag + (uint32_t)((ntp*16*FLS + kt*8) * 4));
                unsigned c0[2] = { bv[0], bv[1] };
                unsigned c1[2] = { bv[2], bv[3] };
                #pragma unroll
                for (int mt = 0; mt < 2; mt++) {
                    mma_tf32(O[mt][2*ntp  ], af[mt], c0);
                    mma_tf32(O[mt][2*ntp+1], af[mt], c1);
                }
            }
        }
        __syncthreads();
    }

    // epilogue: normalize, round, store [B,T,H,HS]
    #pragma unroll
    for (int mt = 0; mt < 2; mt++) {
        float inv0 = 1.0f / l_[2*mt], inv1 = 1.0f / l_[2*mt+1];
        int tq = q0 + r0 + mt*16;
        float* o0 = g_MH + ((size_t)(b * T_ + tq    ) * H_ + h) * HS_;
        float* o1 = g_MH + ((size_t)(b * T_ + tq + 8) * H_ + h) * HS_;
        #pragma unroll
        for (int nt = 0; nt < 8; nt++) {
            *(float2*)&o0[nt*8 + 2*q] =
                make_float2(to_tf32(O[mt][nt][0]*inv0), to_tf32(O[mt][nt][1]*inv0));
            *(float2*)&o1[nt*8 + 2*q] =
                make_float2(to_tf32(O[mt][nt][2]*inv1), to_tf32(O[mt][nt][3]*inv1));
        }
    }
}

// ---------------------------------------------------------------------------
extern "C" void kernel_launch(void* const* d_in, const int* in_sizes, int n_in,
                              void* d_out, int out_size)
{
    const float* query = (const float*)d_in[0];
    const float* key   = (const float*)d_in[1];
    const float* value = (const float*)d_in[2];
    const float* wq    = (const float*)d_in[3];
    const float* wk    = (const float*)d_in[4];
    const float* wv    = (const float*)d_in[5];
    const float* wp    = (const float*)d_in[6];
    const float* bias  = (const float*)d_in[7];
    float* out = (float*)d_out;

    cudaFuncSetAttribute(qkv_g,   cudaFuncAttributeMaxDynamicSharedMemorySize, G_SMEM);
    cudaFuncSetAttribute(out_g,   cudaFuncAttributeMaxDynamicSharedMemorySize, G_SMEM);
    cudaFuncSetAttribute(flash_g, cudaFuncAttributeMaxDynamicSharedMemorySize, FL_SMEM);

    prep_inputs <<<(B_*T_*D_/4 + 255)/256, 256>>>(query, key, value);
    prep_weights<<<dim3(8, 8, 4), 256>>>(wq, wk, wv, wp);
    qkv_g <<<dim3(T_/128, D_/128, 3*B_), 256, G_SMEM>>>();
    flash_g<<<dim3(T_/128, H_, B_), 128, FL_SMEM>>>();
    out_g <<<dim3((B_*T_)/128, D_/128), 256, G_SMEM>>>(bias, out);
}

// round 13
// speedup vs baseline: 7.9714x; 1.7417x over previous
#include <cuda_runtime.h>
#include <cuda_fp16.h>
#include <cstdint>

// Problem constants
constexpr int B_  = 2;
constexpr int T_  = 2048;
constexpr int S_  = 2048;
constexpr int D_  = 512;
constexpr int H_  = 8;
constexpr int HS_ = 64;

// Scratch (device globals). All mma operands stored as fp16 (10-bit mantissa,
// same precision as tf32 for these O(1) values). Accumulation is fp32.
__device__ __half g_Qh [B_*H_*T_*HS_];   // [B,H,T,HS] scaled by 0.125*log2e
__device__ __half g_Kh [B_*H_*S_*HS_];   // [B,H,S,HS]
__device__ __half g_Vth[B_*H_*HS_*S_];   // [B,H,HS,S]  (transposed V)
__device__ __half g_MHh[B_*T_*H_*HS_];   // [B,T,H,HS]
__device__ __half g_XRh[3][B_*T_*D_];    // q/k/v inputs
__device__ __half g_WTh[3][D_*D_];       // qkv weights, [n=h*64+hs][k]
__device__ __half g_WPTh[D_*D_];         // proj weight, [n][k]

// ---------------------------------------------------------------------------
// helpers
// ---------------------------------------------------------------------------
__device__ __forceinline__ void mma_f16(float d[4], const unsigned a[4], const unsigned b[2]) {
    asm volatile(
        "mma.sync.aligned.m16n8k16.row.col.f32.f16.f16.f32 "
        "{%0,%1,%2,%3}, {%4,%5,%6,%7}, {%8,%9}, {%0,%1,%2,%3};"
        : "+f"(d[0]), "+f"(d[1]), "+f"(d[2]), "+f"(d[3])
        : "r"(a[0]), "r"(a[1]), "r"(a[2]), "r"(a[3]),
          "r"(b[0]), "r"(b[1]));
}

__device__ __forceinline__ void ldsm4(unsigned r[4], uint32_t addr) {
    asm volatile("ldmatrix.sync.aligned.m8n8.x4.shared.b16 {%0,%1,%2,%3}, [%4];"
        : "=r"(r[0]), "=r"(r[1]), "=r"(r[2]), "=r"(r[3]) : "r"(addr));
}

__device__ __forceinline__ float ex2(float x) {
    float y; asm("ex2.approx.ftz.f32 %0, %1;" : "=f"(y) : "f"(x)); return y;
}

__device__ __forceinline__ void cp16(uint32_t dst, const void* src) {
    asm volatile("cp.async.ca.shared.global [%0], [%1], 16;" :: "r"(dst), "l"(src));
}
#define CP_COMMIT()  asm volatile("cp.async.commit_group;")
#define CP_WAIT(n)   asm volatile("cp.async.wait_group %0;" :: "n"(n))

__device__ __forceinline__ uint32_t smem_u32_of(const void* p) {
    return (uint32_t)__cvta_generic_to_shared(p);
}

constexpr float QSCALE = 0.125f * 1.4426950408889634f;   // 1/sqrt(HS) * log2(e)

// ---------------------------------------------------------------------------
// Pre-pass 1: convert q/k/v inputs to fp16
// ---------------------------------------------------------------------------
__global__ __launch_bounds__(256) void prep_inputs(
    const float* __restrict__ q, const float* __restrict__ k, const float* __restrict__ v)
{
    int i = blockIdx.x * 256 + threadIdx.x;
    if (i >= B_*T_*D_/4) return;
    float4 a = ((const float4*)q)[i], b = ((const float4*)k)[i], c = ((const float4*)v)[i];
    __half2* d0 = (__half2*)g_XRh[0];
    __half2* d1 = (__half2*)g_XRh[1];
    __half2* d2 = (__half2*)g_XRh[2];
    d0[2*i]   = __floats2half2_rn(a.x, a.y);
    d0[2*i+1] = __floats2half2_rn(a.z, a.w);
    d1[2*i]   = __floats2half2_rn(b.x, b.y);
    d1[2*i+1] = __floats2half2_rn(b.z, b.w);
    d2[2*i]   = __floats2half2_rn(c.x, c.y);
    d2[2*i+1] = __floats2half2_rn(c.z, c.w);
}

// ---------------------------------------------------------------------------
// Pre-pass 2: tiled transpose + fp16 convert of weights into [n][k] form.
// grid (8, 8, 4): 64x64 tiles; z = which (0/1/2 = wq/wk/wv, 3 = wp)
// ---------------------------------------------------------------------------
__global__ __launch_bounds__(256) void prep_weights(
    const float* __restrict__ wq, const float* __restrict__ wk,
    const float* __restrict__ wv, const float* __restrict__ wp)
{
    __shared__ float t[64][65];
    const int which = blockIdx.z;
    const int k0 = blockIdx.x * 64, n0 = blockIdx.y * 64;
    const int tid = threadIdx.x;
    const float* srcw = (which == 0) ? wq : (which == 1) ? wk : (which == 2) ? wv : wp;

    #pragma unroll
    for (int i = 0; i < 16; i++) {
        int e = tid + i * 256;
        int r = e >> 6, c = e & 63;     // r = k-local, c = n-local
        float v;
        if (which == 3) v = srcw[(size_t)(k0 + r) * D_ + n0 + c];
        else            v = srcw[((size_t)(n0 >> 6) * D_ + k0 + r) * HS_ + c];
        t[r][c] = v;
    }
    __syncthreads();
    __half* dst = (which == 3) ? g_WPTh : g_WTh[which];
    #pragma unroll
    for (int i = 0; i < 16; i++) {
        int e = tid + i * 256;
        int nl = e >> 6, kl = e & 63;
        dst[(size_t)(n0 + nl) * D_ + k0 + kl] = __float2half_rn(t[kl][nl]);
    }
}

// ---------------------------------------------------------------------------
// Shared fp16 GEMM body: D[128,128] = A[128,512]h @ Bm[128,512]h^T, f32 accum.
// cp.async 2-stage (k-chunk 64), LDSM fragments. block=256 (8 warps = 4m x 2n)
// ---------------------------------------------------------------------------
constexpr int GSTH  = 72;                      // smem row stride (halfs)
constexpr int GTBH  = 128 * GSTH * 2;          // operand stage bytes (18432)
constexpr int G_SMEM = 2 * 2 * GTBH;           // 73728

template <class Epi>
__device__ __forceinline__ void gemm_body(
    const __half* __restrict__ A, const __half* __restrict__ Bm,
    int row0, int n0, Epi epi)
{
    extern __shared__ __align__(16) char gsm[];
    const uint32_t sb = smem_u32_of(gsm);
    const int tid = threadIdx.x, lane = tid & 31, w = tid >> 5;
    const int wm = w & 3, wn = w >> 2;
    const int p = lane >> 2, q = lane & 3;

    int cr[4], cc[4];
    #pragma unroll
    for (int i = 0; i < 4; i++) {
        int idx = tid + i * 256;                // 1024 16B-chunks per operand
        cr[i] = idx >> 3; cc[i] = (idx & 7) * 8;
    }

    auto issue = [&](int kc) {
        uint32_t ab = sb + (uint32_t)(kc & 1) * (2 * GTBH);
        uint32_t bb = ab + GTBH;
        int k0 = kc * 64;
        #pragma unroll
        for (int i = 0; i < 4; i++) {
            uint32_t off = (uint32_t)((cr[i] * GSTH + cc[i]) * 2);
            cp16(ab + off, A  + (size_t)(row0 + cr[i]) * D_ + k0 + cc[i]);
            cp16(bb + off, Bm + (size_t)(n0   + cr[i]) * D_ + k0 + cc[i]);
        }
        CP_COMMIT();
    };

    issue(0);
    float C[2][8][4] = {};

    for (int kc = 0; kc < 8; kc++) {
        if (kc + 1 < 8) { issue(kc + 1); CP_WAIT(1); }
        else            { CP_WAIT(0); }
        __syncthreads();

        uint32_t ab = sb + (uint32_t)(kc & 1) * (2 * GTBH);
        uint32_t bb = ab + GTBH;
        // A frag: rows (lane&15) of m-block, k-off (lane>>4)*8 halfs
        uint32_t aaddr = ab + (uint32_t)(((wm*32 + (lane&15)) * GSTH + (lane>>4)*8) * 2);
        // B frag: rows (lane&7) of n-group, k-off (lane>>3)*8 halfs
        uint32_t baddr = bb + (uint32_t)(((wn*64 + (lane&7)) * GSTH + (lane>>3)*8) * 2);

        unsigned af[2][4][4];
        #pragma unroll
        for (int mt = 0; mt < 2; mt++)
            #pragma unroll
            for (int kt = 0; kt < 4; kt++)
                ldsm4(af[mt][kt], aaddr + (uint32_t)(mt * 16 * GSTH * 2 + kt * 32));

        #pragma unroll
        for (int nt = 0; nt < 8; nt++) {
            unsigned bq[2][4];
            ldsm4(bq[0], baddr + (uint32_t)(nt * 8 * GSTH * 2));
            ldsm4(bq[1], baddr + (uint32_t)(nt * 8 * GSTH * 2 + 64));
            #pragma unroll
            for (int kt = 0; kt < 4; kt++) {
                unsigned bp[2] = { bq[kt>>1][(kt&1)*2], bq[kt>>1][(kt&1)*2+1] };
                mma_f16(C[0][nt], af[0][kt], bp);
                mma_f16(C[1][nt], af[1][kt], bp);
            }
        }
        __syncthreads();
    }

    #pragma unroll
    for (int mt = 0; mt < 2; mt++) {
        int r = row0 + wm*32 + mt*16 + p;
        #pragma unroll
        for (int nt = 0; nt < 8; nt++) {
            int c = n0 + wn*64 + nt*8 + 2*q;
            epi(r, c, C[mt][nt][0], C[mt][nt][1], C[mt][nt][2], C[mt][nt][3]);
        }
    }
}

// ---------------------------------------------------------------------------
// Kernel 1: QKV projection. grid (T/128, 4, 3B), block 256.
// ---------------------------------------------------------------------------
__global__ __launch_bounds__(256, 2) void qkv_g()
{
    const int which = blockIdx.z % 3;
    const int b     = blockIdx.z / 3;
    const int n0    = blockIdx.y * 128;
    const int row0  = blockIdx.x * 128;

    const __half* A  = g_XRh[which] + (size_t)b * T_ * D_;
    const __half* Bm = g_WTh[which];

    if (which == 0) {
        gemm_body(A, Bm, row0, n0, [&](int r, int c, float v0, float v1, float v2, float v3) {
            int head = c >> 6, hs = c & 63;
            __half* o0 = g_Qh + ((size_t)(b*H_ + head) * T_ + r    ) * HS_ + hs;
            __half* o1 = g_Qh + ((size_t)(b*H_ + head) * T_ + r + 8) * HS_ + hs;
            *(__half2*)o0 = __floats2half2_rn(v0*QSCALE, v1*QSCALE);
            *(__half2*)o1 = __floats2half2_rn(v2*QSCALE, v3*QSCALE);
        });
    } else if (which == 1) {
        gemm_body(A, Bm, row0, n0, [&](int r, int c, float v0, float v1, float v2, float v3) {
            int head = c >> 6, hs = c & 63;
            __half* o0 = g_Kh + ((size_t)(b*H_ + head) * T_ + r    ) * HS_ + hs;
            __half* o1 = g_Kh + ((size_t)(b*H_ + head) * T_ + r + 8) * HS_ + hs;
            *(__half2*)o0 = __floats2half2_rn(v0, v1);
            *(__half2*)o1 = __floats2half2_rn(v2, v3);
        });
    } else {
        gemm_body(A, Bm, row0, n0, [&](int r, int c, float v0, float v1, float v2, float v3) {
            int head = c >> 6, hs = c & 63;
            __half* base = g_Vth + ((size_t)(b*H_ + head) * HS_ + hs) * S_;
            base[r]          = __float2half_rn(v0);
            base[S_ + r]     = __float2half_rn(v1);
            base[r + 8]      = __float2half_rn(v2);
            base[S_ + r + 8] = __float2half_rn(v3);
        });
    }
}

// ---------------------------------------------------------------------------
// Kernel 3: output projection. grid (32, 4), block 256.
// ---------------------------------------------------------------------------
__global__ __launch_bounds__(256, 2) void out_g(const float* __restrict__ bias,
                                                float* __restrict__ out)
{
    const int n0   = blockIdx.y * 128;
    const int row0 = blockIdx.x * 128;
    gemm_body(g_MHh, g_WPTh, row0, n0, [&](int r, int c, float v0, float v1, float v2, float v3) {
        float2 bb = *(const float2*)&bias[c];
        *(float2*)&out[(size_t)r     * D_ + c] = make_float2(v0 + bb.x, v1 + bb.y);
        *(float2*)&out[(size_t)(r+8) * D_ + c] = make_float2(v2 + bb.x, v3 + bb.y);
    });
}

// ---------------------------------------------------------------------------
// Kernel 2: flash attention, fp16. grid (T/128, H, B), block 128 (4 warps x 32 rows).
// SMEM (halfs): Q[128][72] (-> P buffer), 2 stages of K[64][72] + Vt[64][72].
// ---------------------------------------------------------------------------
constexpr int HST      = 72;
constexpr int NT       = S_ / 64;
constexpr int FL_SMEMH = (128 + 4*64) * HST * 2;   // 55296 B

__global__ __launch_bounds__(128, 2) void flash_g()
{
    extern __shared__ __align__(16) __half smh[];
    const uint32_t sb = smem_u32_of(smh);

    const int b    = blockIdx.z;
    const int h    = blockIdx.y;
    const int q0   = blockIdx.x * 128;
    const int tid  = threadIdx.x;
    const int w    = tid >> 5;           // 4 warps
    const int lane = tid & 31;
    const int p    = lane >> 2;
    const int q    = lane & 3;
    const int r0   = w * 32 + p;         // warp owns rows [w*32, w*32+32)

    const __half* Qg  = g_Qh  + ((size_t)(b * H_ + h) * T_ + q0) * HS_;
    const __half* Kg  = g_Kh  + (size_t)(b * H_ + h) * S_ * HS_;
    const __half* Vtg = g_Vth + (size_t)(b * H_ + h) * HS_ * S_;

    // prologue: Q tile (128x64h) = 1024 16B chunks, 8/thread
    #pragma unroll
    for (int i = 0; i < 8; i++) {
        int idx = tid + i * 128;
        int r = idx >> 3, c = (idx & 7) * 8;
        cp16(sb + (uint32_t)((r*HST + c)*2), Qg + (size_t)r*HS_ + c);
    }
    CP_COMMIT();

    auto issue_tile = [&](int t, int s) {
        const uint32_t kb = sb + (uint32_t)((128 + s*128) * HST * 2);
        const uint32_t vb = kb + (uint32_t)(64 * HST * 2);
        #pragma unroll
        for (int i = 0; i < 4; i++) {
            int idx = tid + i * 128;
            int r = idx >> 3, c = (idx & 7) * 8;
            uint32_t doff = (uint32_t)((r*HST + c)*2);
            cp16(kb + doff, Kg  + ((size_t)t*64 + r) * HS_ + c);      // K[s][d]
            cp16(vb + doff, Vtg + (size_t)r*S_ + (size_t)t*64 + c);   // Vt[hs][s]
        }
        CP_COMMIT();
    };

    issue_tile(0, 0);
    CP_WAIT(1);
    __syncthreads();

    // fragment base addresses
    const uint32_t qaddr = sb + (uint32_t)(((w*32 + (lane&15)) * HST + (lane>>4)*8) * 2);
    const uint32_t kvoff = (uint32_t)(((lane&7) * HST + (lane>>3)*8) * 2);

    // Q fragments: 2 m-tiles x 4 k16-tiles (32 regs), persistent
    unsigned qf[2][4][4];
    #pragma unroll
    for (int mt = 0; mt < 2; mt++)
        #pragma unroll
        for (int kt = 0; kt < 4; kt++)
            ldsm4(qf[mt][kt], qaddr + (uint32_t)(mt * 16 * HST * 2 + kt * 32));

    float O[2][8][4] = {};
    float m_[4] = {-1e30f, -1e30f, -1e30f, -1e30f};
    float l_[4] = {0.f, 0.f, 0.f, 0.f};

    for (int t = 0; t < NT; t++) {
        if (t + 1 < NT) { issue_tile(t + 1, (t + 1) & 1); CP_WAIT(1); }
        else            { CP_WAIT(0); }
        __syncthreads();

        const uint32_t kb = sb + (uint32_t)((128 + (t & 1)*128) * HST * 2);
        const uint32_t vb = kb + (uint32_t)(64 * HST * 2);

        // S = Q @ K^T
        float Sf[2][8][4] = {};
        #pragma unroll
        for (int nt = 0; nt < 8; nt++) {
            unsigned bq[2][4];
            ldsm4(bq[0], kb + kvoff + (uint32_t)(nt * 8 * HST * 2));
            ldsm4(bq[1], kb + kvoff + (uint32_t)(nt * 8 * HST * 2 + 64));
            #pragma unroll
            for (int kt = 0; kt < 4; kt++) {
                unsigned bp[2] = { bq[kt>>1][(kt&1)*2], bq[kt>>1][(kt&1)*2+1] };
                mma_f16(Sf[0][nt], qf[0][kt], bp);
                mma_f16(Sf[1][nt], qf[1][kt], bp);
            }
        }

        // online softmax; row groups: 2*mt + half -> row r0 + mt*16 + half*8
        float tm[4] = {-1e30f, -1e30f, -1e30f, -1e30f};
        #pragma unroll
        for (int mt = 0; mt < 2; mt++)
            #pragma unroll
            for (int nt = 0; nt < 8; nt++) {
                tm[2*mt  ] = fmaxf(tm[2*mt  ], fmaxf(Sf[mt][nt][0], Sf[mt][nt][1]));
                tm[2*mt+1] = fmaxf(tm[2*mt+1], fmaxf(Sf[mt][nt][2], Sf[mt][nt][3]));
            }
        float mn[4], al[4], ts[4];
        #pragma unroll
        for (int i = 0; i < 4; i++) {
            tm[i] = fmaxf(tm[i], __shfl_xor_sync(0xffffffffu, tm[i], 1));
            tm[i] = fmaxf(tm[i], __shfl_xor_sync(0xffffffffu, tm[i], 2));
            mn[i] = fmaxf(m_[i], tm[i]);
            al[i] = ex2(m_[i] - mn[i]);
            ts[i] = 0.f;
        }

        #pragma unroll
        for (int mt = 0; mt < 2; mt++)
            #pragma unroll
            for (int nt = 0; nt < 8; nt++) {
                float p00 = ex2(Sf[mt][nt][0] - mn[2*mt  ]);
                float p01 = ex2(Sf[mt][nt][1] - mn[2*mt  ]);
                float p10 = ex2(Sf[mt][nt][2] - mn[2*mt+1]);
                float p11 = ex2(Sf[mt][nt][3] - mn[2*mt+1]);
                ts[2*mt  ] += p00 + p01;
                ts[2*mt+1] += p10 + p11;
                *(__half2*)(smh + (size_t)(r0 + mt*16    )*HST + nt*8 + 2*q) =
                    __floats2half2_rn(p00, p01);
                *(__half2*)(smh + (size_t)(r0 + mt*16 + 8)*HST + nt*8 + 2*q) =
                    __floats2half2_rn(p10, p11);
            }

        #pragma unroll
        for (int i = 0; i < 4; i++) {
            ts[i] += __shfl_xor_sync(0xffffffffu, ts[i], 1);
            ts[i] += __shfl_xor_sync(0xffffffffu, ts[i], 2);
            l_[i] = l_[i] * al[i] + ts[i];
            m_[i] = mn[i];
        }

        #pragma unroll
        for (int mt = 0; mt < 2; mt++)
            #pragma unroll
            for (int nt = 0; nt < 8; nt++) {
                O[mt][nt][0] *= al[2*mt  ]; O[mt][nt][1] *= al[2*mt  ];
                O[mt][nt][2] *= al[2*mt+1]; O[mt][nt][3] *= al[2*mt+1];
            }
        __syncwarp();   // order P stores (warp-private rows) before LDSM reads

        // O += P @ V  (Vt in SMEM: rows = hs, cols = s)
        unsigned af[2][4][4];
        #pragma unroll
        for (int mt = 0; mt < 2; mt++)
            #pragma unroll
            for (int kt = 0; kt < 4; kt++)
                ldsm4(af[mt][kt], qaddr + (uint32_t)(mt * 16 * HST * 2 + kt * 32));
        #pragma unroll
        for (int nt = 0; nt < 8; nt++) {
            unsigned bv[2][4];
            ldsm4(bv[0], vb + kvoff + (uint32_t)(nt * 8 * HST * 2));
            ldsm4(bv[1], vb + kvoff + (uint32_t)(nt * 8 * HST * 2 + 64));
            #pragma unroll
            for (int kt = 0; kt < 4; kt++) {
                unsigned bp[2] = { bv[kt>>1][(kt&1)*2], bv[kt>>1][(kt&1)*2+1] };
                mma_f16(O[0][nt], af[0][kt], bp);
                mma_f16(O[1][nt], af[1][kt], bp);
            }
        }
        __syncthreads();
    }

    // epilogue: normalize, convert to fp16 (A operand of out-proj), store [B,T,H,HS]
    #pragma unroll
    for (int mt = 0; mt < 2; mt++) {
        float inv0 = 1.0f / l_[2*mt], inv1 = 1.0f / l_[2*mt+1];
        int tq = q0 + r0 + mt*16;
        __half* o0 = g_MHh + ((size_t)(b * T_ + tq    ) * H_ + h) * HS_;
        __half* o1 = g_MHh + ((size_t)(b * T_ + tq + 8) * H_ + h) * HS_;
        #pragma unroll
        for (int nt = 0; nt < 8; nt++) {
            *(__half2*)&o0[nt*8 + 2*q] =
                __floats2half2_rn(O[mt][nt][0]*inv0, O[mt][nt][1]*inv0);
            *(__half2*)&o1[nt*8 + 2*q] =
                __floats2half2_rn(O[mt][nt][2]*inv1, O[mt][nt][3]*inv1);
        }
    }
}

// ---------------------------------------------------------------------------
extern "C" void kernel_launch(void* const* d_in, const int* in_sizes, int n_in,
                              void* d_out, int out_size)
{
    const float* query = (const float*)d_in[0];
    const float* key   = (const float*)d_in[1];
    const float* value = (const float*)d_in[2];
    const float* wq    = (const float*)d_in[3];
    const float* wk    = (const float*)d_in[4];
    const float* wv    = (const float*)d_in[5];
    const float* wp    = (const float*)d_in[6];
    const float* bias  = (const float*)d_in[7];
    float* out = (float*)d_out;

    cudaFuncSetAttribute(qkv_g,   cudaFuncAttributeMaxDynamicSharedMemorySize, G_SMEM);
    cudaFuncSetAttribute(out_g,   cudaFuncAttributeMaxDynamicSharedMemorySize, G_SMEM);
    cudaFuncSetAttribute(flash_g, cudaFuncAttributeMaxDynamicSharedMemorySize, FL_SMEMH);

    prep_inputs <<<(B_*T_*D_/4 + 255)/256, 256>>>(query, key, value);
    prep_weights<<<dim3(8, 8, 4), 256>>>(wq, wk, wv, wp);
    qkv_g <<<dim3(T_/128, D_/128, 3*B_), 256, G_SMEM>>>();
    flash_g<<<dim3(T_/128, H_, B_), 128, FL_SMEMH>>>();
    out_g <<<dim3((B_*T_)/128, D_/128), 256, G_SMEM>>>(bias, out);
}

// round 16
// speedup vs baseline: 8.2710x; 1.0376x over previous
#include <cuda_runtime.h>
#include <cuda_fp16.h>
#include <cstdint>

// Problem constants
constexpr int B_  = 2;
constexpr int T_  = 2048;
constexpr int S_  = 2048;
constexpr int D_  = 512;
constexpr int H_  = 8;
constexpr int HS_ = 64;

// Scratch (device globals). All mma operands stored as fp16 (10-bit mantissa,
// same precision as tf32 for these O(1) values). Accumulation is fp32.
__device__ __half g_Qh [B_*H_*T_*HS_];   // [B,H,T,HS] scaled by 0.125*log2e
__device__ __half g_Kh [B_*H_*S_*HS_];   // [B,H,S,HS]
__device__ __half g_Vth[B_*H_*HS_*S_];   // [B,H,HS,S]  (transposed V)
__device__ __half g_MHh[B_*T_*H_*HS_];   // [B,T,H,HS]
__device__ __half g_XRh[3][B_*T_*D_];    // q/k/v inputs
__device__ __half g_WTh[3][D_*D_];       // qkv weights, [n=h*64+hs][k]
__device__ __half g_WPTh[D_*D_];         // proj weight, [n][k]

// ---------------------------------------------------------------------------
// helpers
// ---------------------------------------------------------------------------
__device__ __forceinline__ void mma_f16(float d[4], const unsigned a[4], const unsigned b[2]) {
    asm volatile(
        "mma.sync.aligned.m16n8k16.row.col.f32.f16.f16.f32 "
        "{%0,%1,%2,%3}, {%4,%5,%6,%7}, {%8,%9}, {%0,%1,%2,%3};"
        : "+f"(d[0]), "+f"(d[1]), "+f"(d[2]), "+f"(d[3])
        : "r"(a[0]), "r"(a[1]), "r"(a[2]), "r"(a[3]),
          "r"(b[0]), "r"(b[1]));
}

__device__ __forceinline__ void ldsm4(unsigned r[4], uint32_t addr) {
    asm volatile("ldmatrix.sync.aligned.m8n8.x4.shared.b16 {%0,%1,%2,%3}, [%4];"
        : "=r"(r[0]), "=r"(r[1]), "=r"(r[2]), "=r"(r[3]) : "r"(addr));
}

__device__ __forceinline__ float ex2(float x) {
    float y; asm("ex2.approx.ftz.f32 %0, %1;" : "=f"(y) : "f"(x)); return y;
}

__device__ __forceinline__ unsigned packh2(float lo, float hi) {
    __half2 h = __floats2half2_rn(lo, hi);
    return *(unsigned*)&h;
}

__device__ __forceinline__ void cp16(uint32_t dst, const void* src) {
    asm volatile("cp.async.ca.shared.global [%0], [%1], 16;" :: "r"(dst), "l"(src));
}
#define CP_COMMIT()  asm volatile("cp.async.commit_group;")
#define CP_WAIT(n)   asm volatile("cp.async.wait_group %0;" :: "n"(n))

__device__ __forceinline__ uint32_t smem_u32_of(const void* p) {
    return (uint32_t)__cvta_generic_to_shared(p);
}

constexpr float QSCALE = 0.125f * 1.4426950408889634f;   // 1/sqrt(HS) * log2(e)

// ---------------------------------------------------------------------------
// Pre-pass 1: convert q/k/v inputs to fp16
// ---------------------------------------------------------------------------
__global__ __launch_bounds__(256) void prep_inputs(
    const float* __restrict__ q, const float* __restrict__ k, const float* __restrict__ v)
{
    int i = blockIdx.x * 256 + threadIdx.x;
    if (i >= B_*T_*D_/4) return;
    float4 a = ((const float4*)q)[i], b = ((const float4*)k)[i], c = ((const float4*)v)[i];
    __half2* d0 = (__half2*)g_XRh[0];
    __half2* d1 = (__half2*)g_XRh[1];
    __half2* d2 = (__half2*)g_XRh[2];
    d0[2*i]   = __floats2half2_rn(a.x, a.y);
    d0[2*i+1] = __floats2half2_rn(a.z, a.w);
    d1[2*i]   = __floats2half2_rn(b.x, b.y);
    d1[2*i+1] = __floats2half2_rn(b.z, b.w);
    d2[2*i]   = __floats2half2_rn(c.x, c.y);
    d2[2*i+1] = __floats2half2_rn(c.z, c.w);
}

// ---------------------------------------------------------------------------
// Pre-pass 2: tiled transpose + fp16 convert of weights into [n][k] form.
// grid (8, 8, 4): 64x64 tiles; z = which (0/1/2 = wq/wk/wv, 3 = wp)
// ---------------------------------------------------------------------------
__global__ __launch_bounds__(256) void prep_weights(
    const float* __restrict__ wq, const float* __restrict__ wk,
    const float* __restrict__ wv, const float* __restrict__ wp)
{
    __shared__ float t[64][65];
    const int which = blockIdx.z;
    const int k0 = blockIdx.x * 64, n0 = blockIdx.y * 64;
    const int tid = threadIdx.x;
    const float* srcw = (which == 0) ? wq : (which == 1) ? wk : (which == 2) ? wv : wp;

    #pragma unroll
    for (int i = 0; i < 16; i++) {
        int e = tid + i * 256;
        int r = e >> 6, c = e & 63;     // r = k-local, c = n-local
        float v;
        if (which == 3) v = srcw[(size_t)(k0 + r) * D_ + n0 + c];
        else            v = srcw[((size_t)(n0 >> 6) * D_ + k0 + r) * HS_ + c];
        t[r][c] = v;
    }
    __syncthreads();
    __half* dst = (which == 3) ? g_WPTh : g_WTh[which];
    #pragma unroll
    for (int i = 0; i < 16; i++) {
        int e = tid + i * 256;
        int nl = e >> 6, kl = e & 63;
        dst[(size_t)(n0 + nl) * D_ + k0 + kl] = __float2half_rn(t[kl][nl]);
    }
}

// ---------------------------------------------------------------------------
// Shared fp16 GEMM body: D[128,128] = A[128,512]h @ Bm[128,512]h^T, f32 accum.
// cp.async 2-stage (k-chunk 64), LDSM fragments. block=256 (8 warps = 4m x 2n)
// ---------------------------------------------------------------------------
constexpr int GSTH  = 72;                      // smem row stride (halfs)
constexpr int GTBH  = 128 * GSTH * 2;          // operand stage bytes (18432)
constexpr int G_SMEM = 2 * 2 * GTBH;           // 73728

template <class Epi>
__device__ __forceinline__ void gemm_body(
    const __half* __restrict__ A, const __half* __restrict__ Bm,
    int row0, int n0, Epi epi)
{
    extern __shared__ __align__(16) char gsm[];
    const uint32_t sb = smem_u32_of(gsm);
    const int tid = threadIdx.x, lane = tid & 31, w = tid >> 5;
    const int wm = w & 3, wn = w >> 2;
    const int p = lane >> 2, q = lane & 3;

    int cr[4], cc[4];
    #pragma unroll
    for (int i = 0; i < 4; i++) {
        int idx = tid + i * 256;                // 1024 16B-chunks per operand
        cr[i] = idx >> 3; cc[i] = (idx & 7) * 8;
    }

    auto issue = [&](int kc) {
        uint32_t ab = sb + (uint32_t)(kc & 1) * (2 * GTBH);
        uint32_t bb = ab + GTBH;
        int k0 = kc * 64;
        #pragma unroll
        for (int i = 0; i < 4; i++) {
            uint32_t off = (uint32_t)((cr[i] * GSTH + cc[i]) * 2);
            cp16(ab + off, A  + (size_t)(row0 + cr[i]) * D_ + k0 + cc[i]);
            cp16(bb + off, Bm + (size_t)(n0   + cr[i]) * D_ + k0 + cc[i]);
        }
        CP_COMMIT();
    };

    issue(0);
    float C[2][8][4] = {};

    for (int kc = 0; kc < 8; kc++) {
        if (kc + 1 < 8) { issue(kc + 1); CP_WAIT(1); }
        else            { CP_WAIT(0); }
        __syncthreads();

        uint32_t ab = sb + (uint32_t)(kc & 1) * (2 * GTBH);
        uint32_t bb = ab + GTBH;
        uint32_t aaddr = ab + (uint32_t)(((wm*32 + (lane&15)) * GSTH + (lane>>4)*8) * 2);
        uint32_t baddr = bb + (uint32_t)(((wn*64 + (lane&7)) * GSTH + (lane>>3)*8) * 2);

        unsigned af[2][4][4];
        #pragma unroll
        for (int mt = 0; mt < 2; mt++)
            #pragma unroll
            for (int kt = 0; kt < 4; kt++)
                ldsm4(af[mt][kt], aaddr + (uint32_t)(mt * 16 * GSTH * 2 + kt * 32));

        #pragma unroll
        for (int nt = 0; nt < 8; nt++) {
            unsigned bq[2][4];
            ldsm4(bq[0], baddr + (uint32_t)(nt * 8 * GSTH * 2));
            ldsm4(bq[1], baddr + (uint32_t)(nt * 8 * GSTH * 2 + 64));
            #pragma unroll
            for (int kt = 0; kt < 4; kt++) {
                unsigned bp[2] = { bq[kt>>1][(kt&1)*2], bq[kt>>1][(kt&1)*2+1] };
                mma_f16(C[0][nt], af[0][kt], bp);
                mma_f16(C[1][nt], af[1][kt], bp);
            }
        }
        __syncthreads();
    }

    #pragma unroll
    for (int mt = 0; mt < 2; mt++) {
        int r = row0 + wm*32 + mt*16 + p;
        #pragma unroll
        for (int nt = 0; nt < 8; nt++) {
            int c = n0 + wn*64 + nt*8 + 2*q;
            epi(r, c, C[mt][nt][0], C[mt][nt][1], C[mt][nt][2], C[mt][nt][3]);
        }
    }
}

// ---------------------------------------------------------------------------
// Kernel 1: QKV projection. grid (T/128, 4, 3B), block 256.
// ---------------------------------------------------------------------------
__global__ __launch_bounds__(256, 2) void qkv_g()
{
    const int which = blockIdx.z % 3;
    const int b     = blockIdx.z / 3;
    const int n0    = blockIdx.y * 128;
    const int row0  = blockIdx.x * 128;

    const __half* A  = g_XRh[which] + (size_t)b * T_ * D_;
    const __half* Bm = g_WTh[which];

    if (which == 0) {
        gemm_body(A, Bm, row0, n0, [&](int r, int c, float v0, float v1, float v2, float v3) {
            int head = c >> 6, hs = c & 63;
            __half* o0 = g_Qh + ((size_t)(b*H_ + head) * T_ + r    ) * HS_ + hs;
            __half* o1 = g_Qh + ((size_t)(b*H_ + head) * T_ + r + 8) * HS_ + hs;
            *(__half2*)o0 = __floats2half2_rn(v0*QSCALE, v1*QSCALE);
            *(__half2*)o1 = __floats2half2_rn(v2*QSCALE, v3*QSCALE);
        });
    } else if (which == 1) {
        gemm_body(A, Bm, row0, n0, [&](int r, int c, float v0, float v1, float v2, float v3) {
            int head = c >> 6, hs = c & 63;
            __half* o0 = g_Kh + ((size_t)(b*H_ + head) * T_ + r    ) * HS_ + hs;
            __half* o1 = g_Kh + ((size_t)(b*H_ + head) * T_ + r + 8) * HS_ + hs;
            *(__half2*)o0 = __floats2half2_rn(v0, v1);
            *(__half2*)o1 = __floats2half2_rn(v2, v3);
        });
    } else {
        gemm_body(A, Bm, row0, n0, [&](int r, int c, float v0, float v1, float v2, float v3) {
            int head = c >> 6, hs = c & 63;
            __half* base = g_Vth + ((size_t)(b*H_ + head) * HS_ + hs) * S_;
            base[r]          = __float2half_rn(v0);
            base[S_ + r]     = __float2half_rn(v1);
            base[r + 8]      = __float2half_rn(v2);
            base[S_ + r + 8] = __float2half_rn(v3);
        });
    }
}

// ---------------------------------------------------------------------------
// Kernel 3: output projection. grid (32, 4), block 256.
// ---------------------------------------------------------------------------
__global__ __launch_bounds__(256, 2) void out_g(const float* __restrict__ bias,
                                                float* __restrict__ out)
{
    const int n0   = blockIdx.y * 128;
    const int row0 = blockIdx.x * 128;
    gemm_body(g_MHh, g_WPTh, row0, n0, [&](int r, int c, float v0, float v1, float v2, float v3) {
        float2 bb = *(const float2*)&bias[c];
        *(float2*)&out[(size_t)r     * D_ + c] = make_float2(v0 + bb.x, v1 + bb.y);
        *(float2*)&out[(size_t)(r+8) * D_ + c] = make_float2(v2 + bb.x, v3 + bb.y);
    });
}

// ---------------------------------------------------------------------------
// Kernel 2: flash attention, fp16, register-resident P (FA2 trick).
// grid (T/128, H, B), block 128 (4 warps x 32 rows).
// SMEM (halfs): Q[128][72], 2 stages of K[64][72] + Vt[64][72].
// S accumulator fragments are repacked in registers as PV A-operands:
// C(m16n8) cols nt*8+{2q,2q+1} rows {p,p+8}  ==  A(m16k16) a0..a3 for kt=nt/2.
// ---------------------------------------------------------------------------
constexpr int HST      = 72;
constexpr int NT       = S_ / 64;
constexpr int FL_SMEMH = (128 + 4*64) * HST * 2;   // 55296 B

__global__ __launch_bounds__(128, 2) void flash_g()
{
    extern __shared__ __align__(16) __half smh[];
    const uint32_t sb = smem_u32_of(smh);

    const int b    = blockIdx.z;
    const int h    = blockIdx.y;
    const int q0   = blockIdx.x * 128;
    const int tid  = threadIdx.x;
    const int w    = tid >> 5;           // 4 warps
    const int lane = tid & 31;
    const int p    = lane >> 2;
    const int q    = lane & 3;
    const int r0   = w * 32 + p;         // warp owns rows [w*32, w*32+32)

    const __half* Qg  = g_Qh  + ((size_t)(b * H_ + h) * T_ + q0) * HS_;
    const __half* Kg  = g_Kh  + (size_t)(b * H_ + h) * S_ * HS_;
    const __half* Vtg = g_Vth + (size_t)(b * H_ + h) * HS_ * S_;

    // prologue: Q tile (128x64h) = 1024 16B chunks, 8/thread
    #pragma unroll
    for (int i = 0; i < 8; i++) {
        int idx = tid + i * 128;
        int r = idx >> 3, c = (idx & 7) * 8;
        cp16(sb + (uint32_t)((r*HST + c)*2), Qg + (size_t)r*HS_ + c);
    }
    CP_COMMIT();

    auto issue_tile = [&](int t, int s) {
        const uint32_t kb = sb + (uint32_t)((128 + s*128) * HST * 2);
        const uint32_t vb = kb + (uint32_t)(64 * HST * 2);
        #pragma unroll
        for (int i = 0; i < 4; i++) {
            int idx = tid + i * 128;
            int r = idx >> 3, c = (idx & 7) * 8;
            uint32_t doff = (uint32_t)((r*HST + c)*2);
            cp16(kb + doff, Kg  + ((size_t)t*64 + r) * HS_ + c);      // K[s][d]
            cp16(vb + doff, Vtg + (size_t)r*S_ + (size_t)t*64 + c);   // Vt[hs][s]
        }
        CP_COMMIT();
    };

    issue_tile(0, 0);
    CP_WAIT(1);
    __syncthreads();

    // fragment base addresses
    const uint32_t qaddr = sb + (uint32_t)(((w*32 + (lane&15)) * HST + (lane>>4)*8) * 2);
    const uint32_t kvoff = (uint32_t)(((lane&7) * HST + (lane>>3)*8) * 2);

    // Q fragments: 2 m-tiles x 4 k16-tiles (32 regs), persistent
    unsigned qf[2][4][4];
    #pragma unroll
    for (int mt = 0; mt < 2; mt++)
        #pragma unroll
        for (int kt = 0; kt < 4; kt++)
            ldsm4(qf[mt][kt], qaddr + (uint32_t)(mt * 16 * HST * 2 + kt * 32));

    float O[2][8][4] = {};
    float m_[4] = {-1e30f, -1e30f, -1e30f, -1e30f};
    float l_[4] = {0.f, 0.f, 0.f, 0.f};

    for (int t = 0; t < NT; t++) {
        if (t + 1 < NT) { issue_tile(t + 1, (t + 1) & 1); CP_WAIT(1); }
        else            { CP_WAIT(0); }
        __syncthreads();

        const uint32_t kb = sb + (uint32_t)((128 + (t & 1)*128) * HST * 2);
        const uint32_t vb = kb + (uint32_t)(64 * HST * 2);

        // S = Q @ K^T
        float Sf[2][8][4] = {};
        #pragma unroll
        for (int nt = 0; nt < 8; nt++) {
            unsigned bq[2][4];
            ldsm4(bq[0], kb + kvoff + (uint32_t)(nt * 8 * HST * 2));
            ldsm4(bq[1], kb + kvoff + (uint32_t)(nt * 8 * HST * 2 + 64));
            #pragma unroll
            for (int kt = 0; kt < 4; kt++) {
                unsigned bp[2] = { bq[kt>>1][(kt&1)*2], bq[kt>>1][(kt&1)*2+1] };
                mma_f16(Sf[0][nt], qf[0][kt], bp);
                mma_f16(Sf[1][nt], qf[1][kt], bp);
            }
        }

        // online softmax; row groups: 2*mt + half -> row r0 + mt*16 + half*8
        float tm[4] = {-1e30f, -1e30f, -1e30f, -1e30f};
        #pragma unroll
        for (int mt = 0; mt < 2; mt++)
            #pragma unroll
            for (int nt = 0; nt < 8; nt++) {
                tm[2*mt  ] = fmaxf(tm[2*mt  ], fmaxf(Sf[mt][nt][0], Sf[mt][nt][1]));
                tm[2*mt+1] = fmaxf(tm[2*mt+1], fmaxf(Sf[mt][nt][2], Sf[mt][nt][3]));
            }
        float mn[4], al[4], ts[4];
        #pragma unroll
        for (int i = 0; i < 4; i++) {
            tm[i] = fmaxf(tm[i], __shfl_xor_sync(0xffffffffu, tm[i], 1));
            tm[i] = fmaxf(tm[i], __shfl_xor_sync(0xffffffffu, tm[i], 2));
            mn[i] = fmaxf(m_[i], tm[i]);
            al[i] = ex2(m_[i] - mn[i]);
            ts[i] = 0.f;
        }

        // P stays in registers: pk[mt][nt][0] = rows p, pk[mt][nt][1] = rows p+8
        unsigned pk[2][8][2];
        #pragma unroll
        for (int mt = 0; mt < 2; mt++)
            #pragma unroll
            for (int nt = 0; nt < 8; nt++) {
                float p00 = ex2(Sf[mt][nt][0] - mn[2*mt  ]);
                float p01 = ex2(Sf[mt][nt][1] - mn[2*mt  ]);
                float p10 = ex2(Sf[mt][nt][2] - mn[2*mt+1]);
                float p11 = ex2(Sf[mt][nt][3] - mn[2*mt+1]);
                ts[2*mt  ] += p00 + p01;
                ts[2*mt+1] += p10 + p11;
                pk[mt][nt][0] = packh2(p00, p01);
                pk[mt][nt][1] = packh2(p10, p11);
            }

        #pragma unroll
        for (int i = 0; i < 4; i++) {
            ts[i] += __shfl_xor_sync(0xffffffffu, ts[i], 1);
            ts[i] += __shfl_xor_sync(0xffffffffu, ts[i], 2);
            l_[i] = l_[i] * al[i] + ts[i];
            m_[i] = mn[i];
        }

        #pragma unroll
        for (int mt = 0; mt < 2; mt++)
            #pragma unroll
            for (int nt = 0; nt < 8; nt++) {
                O[mt][nt][0] *= al[2*mt  ]; O[mt][nt][1] *= al[2*mt  ];
                O[mt][nt][2] *= al[2*mt+1]; O[mt][nt][3] *= al[2*mt+1];
            }

        // O += P @ V  (P fragments straight from registers; Vt rows = hs)
        #pragma unroll
        for (int nt = 0; nt < 8; nt++) {
            unsigned bv[2][4];
            ldsm4(bv[0], vb + kvoff + (uint32_t)(nt * 8 * HST * 2));
            ldsm4(bv[1], vb + kvoff + (uint32_t)(nt * 8 * HST * 2 + 64));
            #pragma unroll
            for (int kt = 0; kt < 4; kt++) {
                unsigned bp[2] = { bv[kt>>1][(kt&1)*2], bv[kt>>1][(kt&1)*2+1] };
                unsigned a0[4] = { pk[0][2*kt][0], pk[0][2*kt][1],
                                   pk[0][2*kt+1][0], pk[0][2*kt+1][1] };
                unsigned a1[4] = { pk[1][2*kt][0], pk[1][2*kt][1],
                                   pk[1][2*kt+1][0], pk[1][2*kt+1][1] };
                mma_f16(O[0][nt], a0, bp);
                mma_f16(O[1][nt], a1, bp);
            }
        }
        __syncthreads();
    }

    // epilogue: normalize, convert to fp16 (A operand of out-proj), store [B,T,H,HS]
    #pragma unroll
    for (int mt = 0; mt < 2; mt++) {
        float inv0 = 1.0f / l_[2*mt], inv1 = 1.0f / l_[2*mt+1];
        int tq = q0 + r0 + mt*16;
        __half* o0 = g_MHh + ((size_t)(b * T_ + tq    ) * H_ + h) * HS_;
        __half* o1 = g_MHh + ((size_t)(b * T_ + tq + 8) * H_ + h) * HS_;
        #pragma unroll
        for (int nt = 0; nt < 8; nt++) {
            *(__half2*)&o0[nt*8 + 2*q] =
                __floats2half2_rn(O[mt][nt][0]*inv0, O[mt][nt][1]*inv0);
            *(__half2*)&o1[nt*8 + 2*q] =
                __floats2half2_rn(O[mt][nt][2]*inv1, O[mt][nt][3]*inv1);
        }
    }
}

// ---------------------------------------------------------------------------
extern "C" void kernel_launch(void* const* d_in, const int* in_sizes, int n_in,
                              void* d_out, int out_size)
{
    const float* query = (const float*)d_in[0];
    const float* key   = (const float*)d_in[1];
    const float* value = (const float*)d_in[2];
    const float* wq    = (const float*)d_in[3];
    const float* wk    = (const float*)d_in[4];
    const float* wv    = (const float*)d_in[5];
    const float* wp    = (const float*)d_in[6];
    const float* bias  = (const float*)d_in[7];
    float* out = (float*)d_out;

    cudaFuncSetAttribute(qkv_g,   cudaFuncAttributeMaxDynamicSharedMemorySize, G_SMEM);
    cudaFuncSetAttribute(out_g,   cudaFuncAttributeMaxDynamicSharedMemorySize, G_SMEM);
    cudaFuncSetAttribute(flash_g, cudaFuncAttributeMaxDynamicSharedMemorySize, FL_SMEMH);

    prep_inputs <<<(B_*T_*D_/4 + 255)/256, 256>>>(query, key, value);
    prep_weights<<<dim3(8, 8, 4), 256>>>(wq, wk, wv, wp);
    qkv_g <<<dim3(T_/128, D_/128, 3*B_), 256, G_SMEM>>>();
    flash_g<<<dim3(T_/128, H_, B_), 128, FL_SMEMH>>>();
    out_g <<<dim3((B_*T_)/128, D_/128), 256, G_SMEM>>>(bias, out);
}